// round 6
// baseline (speedup 1.0000x reference)
#include <cuda_runtime.h>
#include <cuda_bf16.h>
#include <cstdint>

#define BATCH 2048
#define ENS   32
#define DX    14
#define DZ    14
#define PM_IN 140
#define SM_IN 220
#define BE    (BATCH * ENS)

#define O1_OFF 0
#define O2_OFF (BATCH * ENS * DX)
#define O3_OFF (O2_OFF + BATCH * DX)
#define O4_OFF (O3_OFF + BATCH * DX)
#define O5_OFF (O4_OFF + BATCH * DZ)

// ---------------- scratch globals (uint32 = packed bf16 pair) ----------------
__device__ uint32_t g_xh [(size_t)BE * 96];    // x hi  [BE][192] bf16
__device__ uint32_t g_xl [(size_t)BE * 96];
__device__ uint32_t g_w1h[256 * 96];           // w1^T  [256][192]
__device__ uint32_t g_w1l[256 * 96];
__device__ uint32_t g_w3h[512 * 128];          // w3^T  [512][256]
__device__ uint32_t g_w3l[512 * 128];
__device__ uint32_t g_h1h[(size_t)BE * 128];   // h1    [BE][256]
__device__ uint32_t g_h1l[(size_t)BE * 128];
__device__ float    g_part[(size_t)16 * BE * DX];   // 16 partial slices
__device__ float    g_sens[BATCH * DZ];

// ---------------- helpers ----------------
__device__ __forceinline__ uint32_t smem_u32(const void* p) {
    uint32_t a;
    asm("{ .reg .u64 t; cvta.to.shared.u64 t, %1; cvt.u32.u64 %0, t; }" : "=r"(a) : "l"(p));
    return a;
}
#define CP16(d, s) asm volatile("cp.async.cg.shared.global [%0], [%1], 16;" :: "r"(d), "l"(s))
#define CP_COMMIT() asm volatile("cp.async.commit_group;")
#define CP_WAIT0()  asm volatile("cp.async.wait_group 0;" ::: "memory")
#define CP_WAIT1()  asm volatile("cp.async.wait_group 1;" ::: "memory")

__device__ __forceinline__ void ldsm4(uint32_t (&r)[4], uint32_t addr) {
    asm volatile("ldmatrix.sync.aligned.m8n8.x4.shared.b16 {%0,%1,%2,%3}, [%4];"
                 : "=r"(r[0]), "=r"(r[1]), "=r"(r[2]), "=r"(r[3]) : "r"(addr));
}
__device__ __forceinline__ void mma_bf16(float (&d)[4], const uint32_t (&a)[4],
                                         uint32_t b0, uint32_t b1) {
    asm volatile(
        "mma.sync.aligned.m16n8k16.row.col.f32.bf16.bf16.f32 "
        "{%0,%1,%2,%3}, {%4,%5,%6,%7}, {%8,%9}, {%0,%1,%2,%3};"
        : "+f"(d[0]), "+f"(d[1]), "+f"(d[2]), "+f"(d[3])
        : "r"(a[0]), "r"(a[1]), "r"(a[2]), "r"(a[3]), "r"(b0), "r"(b1));
}
__device__ __forceinline__ void split2(float v0, float v1, uint32_t& hi, uint32_t& lo) {
    __nv_bfloat16 h0 = __float2bfloat16(v0), h1 = __float2bfloat16(v1);
    __nv_bfloat16 g0 = __float2bfloat16(v0 - __bfloat162float(h0));
    __nv_bfloat16 g1 = __float2bfloat16(v1 - __bfloat162float(h1));
    hi = (uint32_t)__bfloat16_as_ushort(h0) | ((uint32_t)__bfloat16_as_ushort(h1) << 16);
    lo = (uint32_t)__bfloat16_as_ushort(g0) | ((uint32_t)__bfloat16_as_ushort(g1) << 16);
}

// ---------------- prep: x -> hi/lo bf16, K padded to 192 ----------------
__global__ void __launch_bounds__(256)
prep_x_kernel(const float* __restrict__ x)
{
    int idx = blockIdx.x * 256 + threadIdx.x;   // BE*96
    int row = idx / 96, p = idx % 96, k = 2 * p;
    float v0 = (k < PM_IN) ? x[(size_t)row * PM_IN + k] : 0.f;
    float v1 = (k + 1 < PM_IN) ? x[(size_t)row * PM_IN + k + 1] : 0.f;
    uint32_t hi, lo;
    split2(v0, v1, hi, lo);
    g_xh[(size_t)row * 96 + p] = hi;
    g_xl[(size_t)row * 96 + p] = lo;
}

// ---------------- prep: weights transposed -> hi/lo bf16 ----------------
__global__ void __launch_bounds__(256)
prep_w_kernel(const float* __restrict__ w1, const float* __restrict__ w3)
{
    int idx = blockIdx.x * 256 + threadIdx.x;
    uint32_t hi, lo;
    if (idx < 256 * 96) {                        // w1 [140][256] -> [256][192]
        int n = idx / 96, p = idx % 96, k = 2 * p;
        float v0 = (k < PM_IN) ? w1[(size_t)k * 256 + n] : 0.f;
        float v1 = (k + 1 < PM_IN) ? w1[(size_t)(k + 1) * 256 + n] : 0.f;
        split2(v0, v1, hi, lo);
        g_w1h[idx] = hi; g_w1l[idx] = lo;
    } else if (idx < 256 * 96 + 512 * 128) {     // w3 [256][512] -> [512][256]
        int i2 = idx - 256 * 96;
        int n = i2 / 128, p = i2 % 128, k = 2 * p;
        split2(w3[(size_t)k * 512 + n], w3[(size_t)(k + 1) * 512 + n], hi, lo);
        g_w3h[i2] = hi; g_w3l[i2] = lo;
    }
}

// ---------------- HMMA split-bf16 GEMM, 16 warps, double-buffered ----------
// C-tile 128x128, BK=64, 16 warps (4x4), warp tile 32x32.
// SMEM: 2 stages x 4 tiles x 16KB = 128KB, + bias + wm2.
// EPI=0: h1 = leaky(acc+bias) split -> g_h1h/g_h1l
// EPI=1: fused wm2 projection -> g_part (16 slices)
template <int KCHUNKS, int EPI>
__global__ void __launch_bounds__(512, 1)
gemm_hmma(const uint32_t* __restrict__ Ah, const uint32_t* __restrict__ Al,
          const uint32_t* __restrict__ Bh, const uint32_t* __restrict__ Bl,
          int kstr,                             // row stride in uint32 (Kpad/2)
          const float* __restrict__ bias, const float* __restrict__ wm2)
{
    extern __shared__ char smem[];
    const uint32_t ub = smem_u32(smem);
    float* biasS = (float*)(smem + 131072);
    float* wm2s  = (float*)(smem + 131584);

    const int tid = threadIdx.x, wid = tid >> 5, lane = tid & 31;
    const int bn = blockIdx.x, bt = blockIdx.y;
    const int mw = (wid >> 2) * 32;              // warp m offset (4 groups)
    const int nw = (wid & 3) * 32;               // warp n offset (4 groups)

    if (tid < 128) biasS[tid] = bias[bn * 128 + tid];
    if (EPI == 1) {
        for (int i = tid; i < 128 * DX; i += 512) {
            int c = i / DX, m = i % DX;
            wm2s[c * 16 + m] = wm2[(size_t)(bn * 128 + c) * DX + m];
        }
    }

    // 8 cp.async per thread per chunk (4096 total / 512 threads)
    auto issue_load = [&](int stage, int kc) {
#pragma unroll
        for (int q = 0; q < 8; q++) {
            int i = tid + 512 * q;
            int t = i >> 10, r = (i >> 3) & 127, c = i & 7;
            const uint32_t* gp;
            int grow;
            if (t == 0)      { gp = Ah; grow = bt * 128 + r; }
            else if (t == 1) { gp = Al; grow = bt * 128 + r; }
            else if (t == 2) { gp = Bh; grow = bn * 128 + r; }
            else             { gp = Bl; grow = bn * 128 + r; }
            const uint32_t* src = gp + (size_t)grow * kstr + kc * 32 + c * 4;
            uint32_t dst = ub + stage * 65536 + t * 16384 + r * 128
                         + ((c * 16) ^ ((r & 7) << 4));
            CP16(dst, src);
        }
        CP_COMMIT();
    };

    float acc[2][4][4];
#pragma unroll
    for (int f = 0; f < 2; f++)
#pragma unroll
        for (int g = 0; g < 4; g++)
#pragma unroll
            for (int e = 0; e < 4; e++) acc[f][g][e] = 0.f;

    issue_load(0, 0);

#pragma unroll 1
    for (int kc = 0; kc < KCHUNKS; kc++) {
        const int s = kc & 1;
        if (kc + 1 < KCHUNKS) {
            issue_load(s ^ 1, kc + 1);
            CP_WAIT1();
        } else {
            CP_WAIT0();
        }
        __syncthreads();

        const uint32_t sb = ub + s * 65536;
#pragma unroll
        for (int k16 = 0; k16 < 4; k16++) {
            uint32_t ah[2][4], al[2][4];
#pragma unroll
            for (int f = 0; f < 2; f++) {
                int mrow = mw + f * 16 + (lane & 15);
                int cb = k16 * 32 + ((lane >> 4) << 4);
                uint32_t off = mrow * 128 + (cb ^ ((mrow & 7) << 4));
                ldsm4(ah[f], sb + off);
                ldsm4(al[f], sb + 16384 + off);
            }
            uint32_t bh[2][4], bl[2][4];
#pragma unroll
            for (int g = 0; g < 2; g++) {
                int nrow = nw + g * 16 + ((lane >> 4) << 3) + (lane & 7);
                int cb = k16 * 32 + (((lane >> 3) & 1) << 4);
                uint32_t off = nrow * 128 + (cb ^ ((nrow & 7) << 4));
                ldsm4(bh[g], sb + 32768 + off);
                ldsm4(bl[g], sb + 49152 + off);
            }
#pragma unroll
            for (int f = 0; f < 2; f++)
#pragma unroll
                for (int g = 0; g < 2; g++) {
                    mma_bf16(acc[f][2 * g],     ah[f], bh[g][0], bh[g][1]);
                    mma_bf16(acc[f][2 * g],     ah[f], bl[g][0], bl[g][1]);
                    mma_bf16(acc[f][2 * g],     al[f], bh[g][0], bh[g][1]);
                    mma_bf16(acc[f][2 * g + 1], ah[f], bh[g][2], bh[g][3]);
                    mma_bf16(acc[f][2 * g + 1], ah[f], bl[g][2], bl[g][3]);
                    mma_bf16(acc[f][2 * g + 1], al[f], bh[g][2], bh[g][3]);
                }
        }
        __syncthreads();
    }

    if (EPI == 0) {
        // h1 = leaky(acc + bias), split to hi/lo, packed pair writes
#pragma unroll
        for (int f = 0; f < 2; f++) {
            int row0 = bt * 128 + mw + f * 16 + (lane >> 2);
#pragma unroll
            for (int nf = 0; nf < 4; nf++) {
                int col = nw + nf * 8 + 2 * (lane & 3);
                float b0 = biasS[col], b1 = biasS[col + 1];
                float v0 = acc[f][nf][0] + b0, v1 = acc[f][nf][1] + b1;
                float v2 = acc[f][nf][2] + b0, v3 = acc[f][nf][3] + b1;
                v0 = v0 >= 0.f ? v0 : 0.01f * v0;
                v1 = v1 >= 0.f ? v1 : 0.01f * v1;
                v2 = v2 >= 0.f ? v2 : 0.01f * v2;
                v3 = v3 >= 0.f ? v3 : 0.01f * v3;
                uint32_t hi, lo;
                int gcol = bn * 128 + col;
                split2(v0, v1, hi, lo);
                g_h1h[(size_t)row0 * 128 + gcol / 2] = hi;
                g_h1l[(size_t)row0 * 128 + gcol / 2] = lo;
                split2(v2, v3, hi, lo);
                g_h1h[(size_t)(row0 + 8) * 128 + gcol / 2] = hi;
                g_h1l[(size_t)(row0 + 8) * 128 + gcol / 2] = lo;
            }
        }
    } else {
        // fused projection: proj[slot][m] = sum_c leaky(acc+b3)[c] * wm2[c][m]
        float proj[4][DX];
#pragma unroll
        for (int s = 0; s < 4; s++)
#pragma unroll
            for (int m = 0; m < DX; m++) proj[s][m] = 0.f;
#pragma unroll
        for (int f = 0; f < 2; f++)
#pragma unroll
            for (int nf = 0; nf < 4; nf++) {
                int col = nw + nf * 8 + 2 * (lane & 3);
#pragma unroll
                for (int e = 0; e < 2; e++) {
                    int c = col + e;
                    float b = biasS[c];
                    float v0 = acc[f][nf][e] + b;
                    float v1 = acc[f][nf][2 + e] + b;
                    v0 = v0 >= 0.f ? v0 : 0.01f * v0;
                    v1 = v1 >= 0.f ? v1 : 0.01f * v1;
                    const float* wr = wm2s + c * 16;
#pragma unroll
                    for (int m = 0; m < DX; m++) {
                        float wv = wr[m];
                        proj[2 * f][m]     += v0 * wv;
                        proj[2 * f + 1][m] += v1 * wv;
                    }
                }
            }
#pragma unroll
        for (int s = 0; s < 4; s++)
#pragma unroll
            for (int m = 0; m < DX; m++) {
                proj[s][m] += __shfl_xor_sync(0xFFFFFFFFu, proj[s][m], 1);
                proj[s][m] += __shfl_xor_sync(0xFFFFFFFFu, proj[s][m], 2);
            }
        if ((lane & 3) == 0) {
            int slice = bn * 4 + (wid & 3);      // 16 slices
#pragma unroll
            for (int s = 0; s < 4; s++) {
                int row = bt * 128 + mw + (s >> 1) * 16 + (lane >> 2) + (s & 1) * 8;
                float* dst = g_part + ((size_t)slice * BE + row) * DX;
#pragma unroll
                for (int m = 0; m < DX; m++) dst[m] = proj[s][m];
            }
        }
    }
}

// ---------------- sensor MLP on 2048 distinct rows ----------------
__global__ void __launch_bounds__(256)
sensor_kernel(const float* __restrict__ raw,
              const float* __restrict__ w2, const float* __restrict__ b2,
              const float* __restrict__ w3, const float* __restrict__ b3,
              const float* __restrict__ w5, const float* __restrict__ b5,
              const float* __restrict__ w6, const float* __restrict__ b6,
              float* __restrict__ sens)
{
    __shared__ float s[4][SM_IN], h1[4][256], h2[4][256], h3[4][64];
    const int tid = threadIdx.x;
    const int row0 = blockIdx.x * 4;

    for (int i = tid; i < 4 * SM_IN; i += 256)
        s[i / SM_IN][i % SM_IN] = raw[(size_t)(row0 + i / SM_IN) * SM_IN + i % SM_IN];
    __syncthreads();
    {
        float acc[4];
#pragma unroll
        for (int r = 0; r < 4; r++) acc[r] = b2[tid];
        for (int k = 0; k < SM_IN; k++) {
            float w = w2[k * 256 + tid];
#pragma unroll
            for (int r = 0; r < 4; r++) acc[r] += s[r][k] * w;
        }
#pragma unroll
        for (int r = 0; r < 4; r++) h1[r][tid] = acc[r] >= 0.f ? acc[r] : 0.01f * acc[r];
    }
    __syncthreads();
    {
        float acc[4];
#pragma unroll
        for (int r = 0; r < 4; r++) acc[r] = b3[tid];
        for (int k = 0; k < 256; k++) {
            float w = w3[k * 256 + tid];
#pragma unroll
            for (int r = 0; r < 4; r++) acc[r] += h1[r][k] * w;
        }
#pragma unroll
        for (int r = 0; r < 4; r++) h2[r][tid] = acc[r] >= 0.f ? acc[r] : 0.01f * acc[r];
    }
    __syncthreads();
    if (tid < 64) {
        float acc[4];
#pragma unroll
        for (int r = 0; r < 4; r++) acc[r] = b5[tid];
        for (int k = 0; k < 256; k++) {
            float w = w5[k * 64 + tid];
#pragma unroll
            for (int r = 0; r < 4; r++) acc[r] += h2[r][k] * w;
        }
#pragma unroll
        for (int r = 0; r < 4; r++) h3[r][tid] = acc[r] >= 0.f ? acc[r] : 0.01f * acc[r];
    }
    __syncthreads();
    if (tid < DZ) {
        float acc[4];
#pragma unroll
        for (int r = 0; r < 4; r++) acc[r] = b6[tid];
        for (int k = 0; k < 64; k++) {
            float w = w6[k * DZ + tid];
#pragma unroll
            for (int r = 0; r < 4; r++) acc[r] += h3[r][k] * w;
        }
#pragma unroll
        for (int r = 0; r < 4; r++) sens[(size_t)(row0 + r) * DZ + tid] = acc[r];
    }
}

// ---------------- EnKF per batch element ----------------
__global__ void __launch_bounds__(256)
enkf_kernel(const float* __restrict__ part, const float* __restrict__ pm_bm2,
            const float* __restrict__ sens,
            const float* __restrict__ on_w1, const float* __restrict__ on_b1,
            const float* __restrict__ on_w2, const float* __restrict__ on_b2,
            float* __restrict__ out1, float* __restrict__ out2,
            float* __restrict__ out3, float* __restrict__ out4,
            float* __restrict__ out5)
{
    const int b = blockIdx.x, tid = threadIdx.x;
    __shared__ float pred[ENS][DX], ez[ENS][DZ], Am[ENS][DX], corr[ENS][DX];
    __shared__ float sm[DX], zm[DZ], rdiag[DZ], hid[32];
    __shared__ float Mm[DX][DX], Km[DX][DZ], aug[DX][2 * DX], fac[DX];

    for (int i = tid; i < ENS * DX; i += 256) {
        int e = i / DX, j = i % DX;
        size_t row = (size_t)b * ENS + e;
        float p = pm_bm2[j];
#pragma unroll
        for (int q = 0; q < 16; q++) p += part[((size_t)q * BE + row) * DX + j];
        pred[e][j] = p;
    }
    for (int i = tid; i < ENS * DZ; i += 256) {
        int e = i / DZ, j = i % DZ;
        int src = (b * ENS + e) % BATCH;
        float v = sens[src * DZ + j];
        ez[e][j] = v;
        out5[(size_t)(b * ENS + e) * DZ + j] = v;
    }
    __syncthreads();
    if (tid < DX) {
        float s1 = 0.f, s2 = 0.f;
        for (int e = 0; e < ENS; e++) { s1 += pred[e][tid]; s2 += ez[e][tid]; }
        float m1 = s1 * (1.f / ENS), m2 = s2 * (1.f / ENS);
        sm[tid] = m1; zm[tid] = m2;
        out3[b * DX + tid] = m1;
        out4[b * DZ + tid] = m2;
    }
    __syncthreads();
    if (tid < 32) {
        float a = on_b1[tid];
        for (int i = 0; i < DZ; i++) a += zm[i] * on_w1[i * 32 + tid];
        hid[tid] = a > 0.f ? a : 0.f;
    }
    __syncthreads();
    if (tid < DZ) {
        float a = on_b2[tid];
        for (int j = 0; j < 32; j++) a += hid[j] * on_w2[j * DZ + tid];
        a += 0.001f;
        rdiag[tid] = a * a + 0.038729833f;
    }
    for (int i = tid; i < ENS * DX; i += 256)
        Am[i / DX][i % DX] = pred[i / DX][i % DX] - sm[i % DX];
    __syncthreads();
    if (tid < DX * DX) {
        int i = tid / DX, j = tid % DX;
        float s = 0.f;
        for (int e = 0; e < ENS; e++) s += Am[e][i] * Am[e][j];
        float m = s * (1.f / (ENS - 1));
        Mm[i][j] = m;
        aug[i][j] = m + (i == j ? rdiag[i] : 0.f);
        aug[i][DX + j] = (i == j) ? 1.f : 0.f;
    }
    __syncthreads();
    for (int p = 0; p < DX; p++) {
        float pv = aug[p][p];
        __syncthreads();
        if (tid < 2 * DX) aug[p][tid] *= (1.f / pv);
        if (tid < DX) fac[tid] = (tid == p) ? 0.f : aug[tid][p];
        __syncthreads();
        for (int t = tid; t < DX * 2 * DX; t += 256) {
            int rr = t / (2 * DX), c = t % (2 * DX);
            if (rr != p) aug[rr][c] -= fac[rr] * aug[p][c];
        }
        __syncthreads();
    }
    if (tid < DX * DX) {
        int i = tid / DX, j = tid % DX;
        float s = 0.f;
        for (int k = 0; k < DX; k++) s += Mm[i][k] * aug[k][DX + j];
        Km[i][j] = s;
    }
    __syncthreads();
    for (int t = tid; t < ENS * DX; t += 256) {
        int e = t / DX, i = t % DX;
        float s = pred[e][i];
        for (int j = 0; j < DZ; j++) s += Km[i][j] * (ez[e][j] - pred[e][j]);
        corr[e][i] = s;
        out1[(size_t)(b * ENS + e) * DX + i] = s;
    }
    __syncthreads();
    if (tid < DX) {
        float s = 0.f;
        for (int e = 0; e < ENS; e++) s += corr[e][tid];
        out2[b * DX + tid] = s * (1.f / ENS);
    }
}

// ---------------- launcher ----------------
extern "C" void kernel_launch(void* const* d_in, const int* in_sizes, int n_in,
                              void* d_out, int out_size)
{
    const float* raw    = (const float*)d_in[0];
    const float* sp     = (const float*)d_in[1];
    const float* pm_w1  = (const float*)d_in[2];
    const float* pm_b1  = (const float*)d_in[3];
    const float* pm_w3  = (const float*)d_in[4];
    const float* pm_b3  = (const float*)d_in[5];
    const float* pm_wm2 = (const float*)d_in[6];
    const float* pm_bm2 = (const float*)d_in[7];
    const float* sm_w2  = (const float*)d_in[8];
    const float* sm_b2  = (const float*)d_in[9];
    const float* sm_w3  = (const float*)d_in[10];
    const float* sm_b3  = (const float*)d_in[11];
    const float* sm_w5  = (const float*)d_in[12];
    const float* sm_b5  = (const float*)d_in[13];
    const float* sm_w6  = (const float*)d_in[14];
    const float* sm_b6  = (const float*)d_in[15];
    const float* on_w1  = (const float*)d_in[16];
    const float* on_b1  = (const float*)d_in[17];
    const float* on_w2  = (const float*)d_in[18];
    const float* on_b2  = (const float*)d_in[19];

    float* out = (float*)d_out;

    uint32_t *xh, *xl, *w1h, *w1l, *w3h, *w3l, *h1h, *h1l;
    float *partp, *sensp;
    cudaGetSymbolAddress((void**)&xh,  g_xh);
    cudaGetSymbolAddress((void**)&xl,  g_xl);
    cudaGetSymbolAddress((void**)&w1h, g_w1h);
    cudaGetSymbolAddress((void**)&w1l, g_w1l);
    cudaGetSymbolAddress((void**)&w3h, g_w3h);
    cudaGetSymbolAddress((void**)&w3l, g_w3l);
    cudaGetSymbolAddress((void**)&h1h, g_h1h);
    cudaGetSymbolAddress((void**)&h1l, g_h1l);
    cudaGetSymbolAddress((void**)&partp, g_part);
    cudaGetSymbolAddress((void**)&sensp, g_sens);

    const int DYN = 131072 + 512 + 8192;   // 2-stage tiles + bias + wm2
    cudaFuncSetAttribute(gemm_hmma<3, 0>, cudaFuncAttributeMaxDynamicSharedMemorySize, DYN);
    cudaFuncSetAttribute(gemm_hmma<4, 1>, cudaFuncAttributeMaxDynamicSharedMemorySize, DYN);

    prep_w_kernel<<<(256 * 96 + 512 * 128 + 255) / 256, 256>>>(pm_w1, pm_w3);
    prep_x_kernel<<<BE * 96 / 256, 256>>>(sp);

    // GEMM A: h1 = leaky(x @ w1 + b1)  [BE x 256], K=192 (padded)
    gemm_hmma<3, 0><<<dim3(2, BE / 128), 512, DYN>>>(xh, xl, w1h, w1l, 96, pm_b1, nullptr);
    // GEMM B: fused leaky(h1 @ w3 + b3) @ wm2 -> partials, K=256
    gemm_hmma<4, 1><<<dim3(4, BE / 128), 512, DYN>>>(h1h, h1l, w3h, w3l, 128, pm_b3, pm_wm2);

    sensor_kernel<<<BATCH / 4, 256>>>(raw, sm_w2, sm_b2, sm_w3, sm_b3,
                                      sm_w5, sm_b5, sm_w6, sm_b6, sensp);
    enkf_kernel<<<BATCH, 256>>>(partp, pm_bm2, sensp, on_w1, on_b1, on_w2, on_b2,
                                out + O1_OFF, out + O2_OFF, out + O3_OFF,
                                out + O4_OFF, out + O5_OFF);
}

// round 7
// speedup vs baseline: 1.0411x; 1.0411x over previous
#include <cuda_runtime.h>
#include <cuda_bf16.h>
#include <cstdint>

#define BATCH 2048
#define ENS   32
#define DX    14
#define DZ    14
#define PM_IN 140
#define SM_IN 220
#define BE    (BATCH * ENS)

#define O1_OFF 0
#define O2_OFF (BATCH * ENS * DX)
#define O3_OFF (O2_OFF + BATCH * DX)
#define O4_OFF (O3_OFF + BATCH * DX)
#define O5_OFF (O4_OFF + BATCH * DZ)

// ---------------- scratch globals (uint32 = packed bf16 pair) ----------------
__device__ uint32_t g_xh [(size_t)BE * 96];    // x hi  [BE][192] bf16
__device__ uint32_t g_xl [(size_t)BE * 96];
__device__ uint32_t g_w1h[256 * 96];           // w1^T  [256][192]
__device__ uint32_t g_w1l[256 * 96];
__device__ uint32_t g_w3h[512 * 128];          // w3^T  [512][256]
__device__ uint32_t g_w3l[512 * 128];
__device__ uint32_t g_h1h[(size_t)BE * 128];   // h1    [BE][256]
__device__ uint32_t g_h1l[(size_t)BE * 128];
__device__ float    g_part[(size_t)8 * BE * DX];   // 8 partial slices
__device__ float    g_sens[BATCH * DZ];

// ---------------- helpers ----------------
__device__ __forceinline__ uint32_t smem_u32(const void* p) {
    uint32_t a;
    asm("{ .reg .u64 t; cvta.to.shared.u64 t, %1; cvt.u32.u64 %0, t; }" : "=r"(a) : "l"(p));
    return a;
}
#define CP16(d, s) asm volatile("cp.async.cg.shared.global [%0], [%1], 16;" :: "r"(d), "l"(s))
#define CP_COMMIT() asm volatile("cp.async.commit_group;")
#define CP_WAIT0()  asm volatile("cp.async.wait_group 0;" ::: "memory")
#define CP_WAIT1()  asm volatile("cp.async.wait_group 1;" ::: "memory")

__device__ __forceinline__ void ldsm4(uint32_t (&r)[4], uint32_t addr) {
    asm volatile("ldmatrix.sync.aligned.m8n8.x4.shared.b16 {%0,%1,%2,%3}, [%4];"
                 : "=r"(r[0]), "=r"(r[1]), "=r"(r[2]), "=r"(r[3]) : "r"(addr));
}
__device__ __forceinline__ void mma_bf16(float (&d)[4], const uint32_t (&a)[4],
                                         uint32_t b0, uint32_t b1) {
    asm volatile(
        "mma.sync.aligned.m16n8k16.row.col.f32.bf16.bf16.f32 "
        "{%0,%1,%2,%3}, {%4,%5,%6,%7}, {%8,%9}, {%0,%1,%2,%3};"
        : "+f"(d[0]), "+f"(d[1]), "+f"(d[2]), "+f"(d[3])
        : "r"(a[0]), "r"(a[1]), "r"(a[2]), "r"(a[3]), "r"(b0), "r"(b1));
}
__device__ __forceinline__ void split2(float v0, float v1, uint32_t& hi, uint32_t& lo) {
    __nv_bfloat16 h0 = __float2bfloat16(v0), h1 = __float2bfloat16(v1);
    __nv_bfloat16 g0 = __float2bfloat16(v0 - __bfloat162float(h0));
    __nv_bfloat16 g1 = __float2bfloat16(v1 - __bfloat162float(h1));
    hi = (uint32_t)__bfloat16_as_ushort(h0) | ((uint32_t)__bfloat16_as_ushort(h1) << 16);
    lo = (uint32_t)__bfloat16_as_ushort(g0) | ((uint32_t)__bfloat16_as_ushort(g1) << 16);
}

// ---------------- prep: x -> hi/lo bf16, K padded to 192 ----------------
__global__ void __launch_bounds__(256)
prep_x_kernel(const float* __restrict__ x)
{
    int idx = blockIdx.x * 256 + threadIdx.x;   // BE*96
    int row = idx / 96, p = idx % 96, k = 2 * p;
    float v0 = (k < PM_IN) ? x[(size_t)row * PM_IN + k] : 0.f;
    float v1 = (k + 1 < PM_IN) ? x[(size_t)row * PM_IN + k + 1] : 0.f;
    uint32_t hi, lo;
    split2(v0, v1, hi, lo);
    g_xh[(size_t)row * 96 + p] = hi;
    g_xl[(size_t)row * 96 + p] = lo;
}

// ---------------- prep: weights transposed -> hi/lo bf16 ----------------
__global__ void __launch_bounds__(256)
prep_w_kernel(const float* __restrict__ w1, const float* __restrict__ w3)
{
    int idx = blockIdx.x * 256 + threadIdx.x;
    uint32_t hi, lo;
    if (idx < 256 * 96) {                        // w1 [140][256] -> [256][192]
        int n = idx / 96, p = idx % 96, k = 2 * p;
        float v0 = (k < PM_IN) ? w1[(size_t)k * 256 + n] : 0.f;
        float v1 = (k + 1 < PM_IN) ? w1[(size_t)(k + 1) * 256 + n] : 0.f;
        split2(v0, v1, hi, lo);
        g_w1h[idx] = hi; g_w1l[idx] = lo;
    } else if (idx < 256 * 96 + 512 * 128) {     // w3 [256][512] -> [512][256]
        int i2 = idx - 256 * 96;
        int n = i2 / 128, p = i2 % 128, k = 2 * p;
        split2(w3[(size_t)k * 512 + n], w3[(size_t)(k + 1) * 512 + n], hi, lo);
        g_w3h[i2] = hi; g_w3l[i2] = lo;
    }
}

// ---------------- HMMA split-bf16 GEMM, warp tile 64x64 -------------------
// CTA tile 128x256, BK=64, 8 warps (2m x 4n). Double-buffered cp.async.
// SMEM/stage: A(h,l) 32KB + B(h,l) 64KB = 96KB; 2 stages = 192KB; +bias+wm2.
// EPI=0: h1 = leaky(acc+bias) split -> g_h1h/g_h1l
// EPI=1: fused wm2 projection -> g_part (8 slices)
template <int KCHUNKS, int EPI>
__global__ void __launch_bounds__(256, 1)
gemm_hmma(const uint32_t* __restrict__ Ah, const uint32_t* __restrict__ Al,
          const uint32_t* __restrict__ Bh, const uint32_t* __restrict__ Bl,
          int kstr,                             // row stride in uint32 (Kpad/2)
          const float* __restrict__ bias, const float* __restrict__ wm2)
{
    extern __shared__ char smem[];
    const uint32_t ub = smem_u32(smem);
    float* biasS = (float*)(smem + 196608);      // 256 floats
    float* wm2s  = (float*)(smem + 197632);      // 256 x 16 floats

    const int tid = threadIdx.x, wid = tid >> 5, lane = tid & 31;
    const int bn = blockIdx.x, bt = blockIdx.y;
    const int mw = (wid >> 2) * 64;              // 2 m-groups
    const int nw = (wid & 3) * 64;               // 4 n-groups

    biasS[tid] = bias[bn * 256 + tid];
    if (EPI == 1) {
        for (int i = tid; i < 256 * DX; i += 256) {
            int c = i / DX, m = i % DX;
            wm2s[c * 16 + m] = wm2[(size_t)(bn * 256 + c) * DX + m];
        }
    }

    // 6144 16B units per chunk / 256 threads = 24 per thread
    auto issue_load = [&](int stage, int kc) {
        const uint32_t sb = ub + stage * 98304;
#pragma unroll
        for (int q = 0; q < 24; q++) {
            int i = tid + 256 * q;
            const uint32_t* src;
            uint32_t dst;
            if (i < 2048) {                      // A tiles: 2 x 16KB, 128 rows
                int t = i >> 10, r = (i >> 3) & 127, c = i & 7;
                const uint32_t* gp = t ? Al : Ah;
                src = gp + (size_t)(bt * 128 + r) * kstr + kc * 32 + c * 4;
                dst = sb + t * 16384 + r * 128 + ((c * 16) ^ ((r & 7) << 4));
            } else {                             // B tiles: 2 x 32KB, 256 rows
                int j = i - 2048;
                int t = j >> 11, r = (j >> 3) & 255, c = j & 7;
                const uint32_t* gp = t ? Bl : Bh;
                src = gp + (size_t)(bn * 256 + r) * kstr + kc * 32 + c * 4;
                dst = sb + 32768 + t * 32768 + r * 128 + ((c * 16) ^ ((r & 7) << 4));
            }
            CP16(dst, src);
        }
        CP_COMMIT();
    };

    float acc[4][8][4];
#pragma unroll
    for (int f = 0; f < 4; f++)
#pragma unroll
        for (int g = 0; g < 8; g++)
#pragma unroll
            for (int e = 0; e < 4; e++) acc[f][g][e] = 0.f;

    issue_load(0, 0);

#pragma unroll 1
    for (int kc = 0; kc < KCHUNKS; kc++) {
        const int s = kc & 1;
        if (kc + 1 < KCHUNKS) {
            issue_load(s ^ 1, kc + 1);
            CP_WAIT1();
        } else {
            CP_WAIT0();
        }
        __syncthreads();

        const uint32_t sb = ub + s * 98304;
#pragma unroll
        for (int k16 = 0; k16 < 4; k16++) {
            uint32_t ah[4][4], al[4][4];
#pragma unroll
            for (int f = 0; f < 4; f++) {
                int mrow = mw + f * 16 + (lane & 15);
                int cb = k16 * 32 + ((lane >> 4) << 4);
                uint32_t off = mrow * 128 + (cb ^ ((mrow & 7) << 4));
                ldsm4(ah[f], sb + off);
                ldsm4(al[f], sb + 16384 + off);
            }
            uint32_t bh[4][4], bl[4][4];
#pragma unroll
            for (int g = 0; g < 4; g++) {
                int nrow = nw + g * 16 + ((lane >> 4) << 3) + (lane & 7);
                int cb = k16 * 32 + (((lane >> 3) & 1) << 4);
                uint32_t off = nrow * 128 + (cb ^ ((nrow & 7) << 4));
                ldsm4(bh[g], sb + 32768 + off);
                ldsm4(bl[g], sb + 65536 + off);
            }
#pragma unroll
            for (int f = 0; f < 4; f++)
#pragma unroll
                for (int g = 0; g < 4; g++) {
                    mma_bf16(acc[f][2 * g],     ah[f], bh[g][0], bh[g][1]);
                    mma_bf16(acc[f][2 * g],     ah[f], bl[g][0], bl[g][1]);
                    mma_bf16(acc[f][2 * g],     al[f], bh[g][0], bh[g][1]);
                    mma_bf16(acc[f][2 * g + 1], ah[f], bh[g][2], bh[g][3]);
                    mma_bf16(acc[f][2 * g + 1], ah[f], bl[g][2], bl[g][3]);
                    mma_bf16(acc[f][2 * g + 1], al[f], bh[g][2], bh[g][3]);
                }
        }
        __syncthreads();
    }

    if (EPI == 0) {
        // h1 = leaky(acc + bias), split to hi/lo, packed pair writes
#pragma unroll
        for (int f = 0; f < 4; f++) {
            int row0 = bt * 128 + mw + f * 16 + (lane >> 2);
#pragma unroll
            for (int nf = 0; nf < 8; nf++) {
                int col = nw + nf * 8 + 2 * (lane & 3);
                float b0 = biasS[col], b1 = biasS[col + 1];
                float v0 = acc[f][nf][0] + b0, v1 = acc[f][nf][1] + b1;
                float v2 = acc[f][nf][2] + b0, v3 = acc[f][nf][3] + b1;
                v0 = v0 >= 0.f ? v0 : 0.01f * v0;
                v1 = v1 >= 0.f ? v1 : 0.01f * v1;
                v2 = v2 >= 0.f ? v2 : 0.01f * v2;
                v3 = v3 >= 0.f ? v3 : 0.01f * v3;
                uint32_t hi, lo;
                int gcol = bn * 256 + col;
                split2(v0, v1, hi, lo);
                g_h1h[(size_t)row0 * 128 + gcol / 2] = hi;
                g_h1l[(size_t)row0 * 128 + gcol / 2] = lo;
                split2(v2, v3, hi, lo);
                g_h1h[(size_t)(row0 + 8) * 128 + gcol / 2] = hi;
                g_h1l[(size_t)(row0 + 8) * 128 + gcol / 2] = lo;
            }
        }
    } else {
        // fused projection, one f-slab at a time to bound registers
#pragma unroll
        for (int f = 0; f < 4; f++) {
            float proj0[DX], proj1[DX];
#pragma unroll
            for (int m = 0; m < DX; m++) { proj0[m] = 0.f; proj1[m] = 0.f; }
#pragma unroll
            for (int nf = 0; nf < 8; nf++) {
                int col = nw + nf * 8 + 2 * (lane & 3);
#pragma unroll
                for (int e = 0; e < 2; e++) {
                    int c = col + e;
                    float b = biasS[c];
                    float v0 = acc[f][nf][e] + b;
                    float v1 = acc[f][nf][2 + e] + b;
                    v0 = v0 >= 0.f ? v0 : 0.01f * v0;
                    v1 = v1 >= 0.f ? v1 : 0.01f * v1;
                    const float* wr = wm2s + c * 16;
#pragma unroll
                    for (int m = 0; m < DX; m++) {
                        float wv = wr[m];
                        proj0[m] += v0 * wv;
                        proj1[m] += v1 * wv;
                    }
                }
            }
#pragma unroll
            for (int m = 0; m < DX; m++) {
                proj0[m] += __shfl_xor_sync(0xFFFFFFFFu, proj0[m], 1);
                proj0[m] += __shfl_xor_sync(0xFFFFFFFFu, proj0[m], 2);
                proj1[m] += __shfl_xor_sync(0xFFFFFFFFu, proj1[m], 1);
                proj1[m] += __shfl_xor_sync(0xFFFFFFFFu, proj1[m], 2);
            }
            if ((lane & 3) == 0) {
                int slice = bn * 4 + (wid & 3);      // 8 slices total
                int row = bt * 128 + mw + f * 16 + (lane >> 2);
                float* d0 = g_part + ((size_t)slice * BE + row) * DX;
                float* d1 = g_part + ((size_t)slice * BE + row + 8) * DX;
#pragma unroll
                for (int m = 0; m < DX; m++) { d0[m] = proj0[m]; d1[m] = proj1[m]; }
            }
        }
    }
}

// ---------------- sensor MLP on 2048 distinct rows ----------------
__global__ void __launch_bounds__(256)
sensor_kernel(const float* __restrict__ raw,
              const float* __restrict__ w2, const float* __restrict__ b2,
              const float* __restrict__ w3, const float* __restrict__ b3,
              const float* __restrict__ w5, const float* __restrict__ b5,
              const float* __restrict__ w6, const float* __restrict__ b6,
              float* __restrict__ sens)
{
    __shared__ float s[4][SM_IN], h1[4][256], h2[4][256], h3[4][64];
    const int tid = threadIdx.x;
    const int row0 = blockIdx.x * 4;

    for (int i = tid; i < 4 * SM_IN; i += 256)
        s[i / SM_IN][i % SM_IN] = raw[(size_t)(row0 + i / SM_IN) * SM_IN + i % SM_IN];
    __syncthreads();
    {
        float acc[4];
#pragma unroll
        for (int r = 0; r < 4; r++) acc[r] = b2[tid];
        for (int k = 0; k < SM_IN; k++) {
            float w = w2[k * 256 + tid];
#pragma unroll
            for (int r = 0; r < 4; r++) acc[r] += s[r][k] * w;
        }
#pragma unroll
        for (int r = 0; r < 4; r++) h1[r][tid] = acc[r] >= 0.f ? acc[r] : 0.01f * acc[r];
    }
    __syncthreads();
    {
        float acc[4];
#pragma unroll
        for (int r = 0; r < 4; r++) acc[r] = b3[tid];
        for (int k = 0; k < 256; k++) {
            float w = w3[k * 256 + tid];
#pragma unroll
            for (int r = 0; r < 4; r++) acc[r] += h1[r][k] * w;
        }
#pragma unroll
        for (int r = 0; r < 4; r++) h2[r][tid] = acc[r] >= 0.f ? acc[r] : 0.01f * acc[r];
    }
    __syncthreads();
    if (tid < 64) {
        float acc[4];
#pragma unroll
        for (int r = 0; r < 4; r++) acc[r] = b5[tid];
        for (int k = 0; k < 256; k++) {
            float w = w5[k * 64 + tid];
#pragma unroll
            for (int r = 0; r < 4; r++) acc[r] += h2[r][k] * w;
        }
#pragma unroll
        for (int r = 0; r < 4; r++) h3[r][tid] = acc[r] >= 0.f ? acc[r] : 0.01f * acc[r];
    }
    __syncthreads();
    if (tid < DZ) {
        float acc[4];
#pragma unroll
        for (int r = 0; r < 4; r++) acc[r] = b6[tid];
        for (int k = 0; k < 64; k++) {
            float w = w6[k * DZ + tid];
#pragma unroll
            for (int r = 0; r < 4; r++) acc[r] += h3[r][k] * w;
        }
#pragma unroll
        for (int r = 0; r < 4; r++) sens[(size_t)(row0 + r) * DZ + tid] = acc[r];
    }
}

// ---------------- EnKF per batch element ----------------
__global__ void __launch_bounds__(256)
enkf_kernel(const float* __restrict__ part, const float* __restrict__ pm_bm2,
            const float* __restrict__ sens,
            const float* __restrict__ on_w1, const float* __restrict__ on_b1,
            const float* __restrict__ on_w2, const float* __restrict__ on_b2,
            float* __restrict__ out1, float* __restrict__ out2,
            float* __restrict__ out3, float* __restrict__ out4,
            float* __restrict__ out5)
{
    const int b = blockIdx.x, tid = threadIdx.x;
    __shared__ float pred[ENS][DX], ez[ENS][DZ], Am[ENS][DX], corr[ENS][DX];
    __shared__ float sm[DX], zm[DZ], rdiag[DZ], hid[32];
    __shared__ float Mm[DX][DX], Km[DX][DZ], aug[DX][2 * DX], fac[DX];

    for (int i = tid; i < ENS * DX; i += 256) {
        int e = i / DX, j = i % DX;
        size_t row = (size_t)b * ENS + e;
        float p = pm_bm2[j];
#pragma unroll
        for (int q = 0; q < 8; q++) p += part[((size_t)q * BE + row) * DX + j];
        pred[e][j] = p;
    }
    for (int i = tid; i < ENS * DZ; i += 256) {
        int e = i / DZ, j = i % DZ;
        int src = (b * ENS + e) % BATCH;
        float v = sens[src * DZ + j];
        ez[e][j] = v;
        out5[(size_t)(b * ENS + e) * DZ + j] = v;
    }
    __syncthreads();
    if (tid < DX) {
        float s1 = 0.f, s2 = 0.f;
        for (int e = 0; e < ENS; e++) { s1 += pred[e][tid]; s2 += ez[e][tid]; }
        float m1 = s1 * (1.f / ENS), m2 = s2 * (1.f / ENS);
        sm[tid] = m1; zm[tid] = m2;
        out3[b * DX + tid] = m1;
        out4[b * DZ + tid] = m2;
    }
    __syncthreads();
    if (tid < 32) {
        float a = on_b1[tid];
        for (int i = 0; i < DZ; i++) a += zm[i] * on_w1[i * 32 + tid];
        hid[tid] = a > 0.f ? a : 0.f;
    }
    __syncthreads();
    if (tid < DZ) {
        float a = on_b2[tid];
        for (int j = 0; j < 32; j++) a += hid[j] * on_w2[j * DZ + tid];
        a += 0.001f;
        rdiag[tid] = a * a + 0.038729833f;
    }
    for (int i = tid; i < ENS * DX; i += 256)
        Am[i / DX][i % DX] = pred[i / DX][i % DX] - sm[i % DX];
    __syncthreads();
    if (tid < DX * DX) {
        int i = tid / DX, j = tid % DX;
        float s = 0.f;
        for (int e = 0; e < ENS; e++) s += Am[e][i] * Am[e][j];
        float m = s * (1.f / (ENS - 1));
        Mm[i][j] = m;
        aug[i][j] = m + (i == j ? rdiag[i] : 0.f);
        aug[i][DX + j] = (i == j) ? 1.f : 0.f;
    }
    __syncthreads();
    for (int p = 0; p < DX; p++) {
        float pv = aug[p][p];
        __syncthreads();
        if (tid < 2 * DX) aug[p][tid] *= (1.f / pv);
        if (tid < DX) fac[tid] = (tid == p) ? 0.f : aug[tid][p];
        __syncthreads();
        for (int t = tid; t < DX * 2 * DX; t += 256) {
            int rr = t / (2 * DX), c = t % (2 * DX);
            if (rr != p) aug[rr][c] -= fac[rr] * aug[p][c];
        }
        __syncthreads();
    }
    if (tid < DX * DX) {
        int i = tid / DX, j = tid % DX;
        float s = 0.f;
        for (int k = 0; k < DX; k++) s += Mm[i][k] * aug[k][DX + j];
        Km[i][j] = s;
    }
    __syncthreads();
    for (int t = tid; t < ENS * DX; t += 256) {
        int e = t / DX, i = t % DX;
        float s = pred[e][i];
        for (int j = 0; j < DZ; j++) s += Km[i][j] * (ez[e][j] - pred[e][j]);
        corr[e][i] = s;
        out1[(size_t)(b * ENS + e) * DX + i] = s;
    }
    __syncthreads();
    if (tid < DX) {
        float s = 0.f;
        for (int e = 0; e < ENS; e++) s += corr[e][tid];
        out2[b * DX + tid] = s * (1.f / ENS);
    }
}

// ---------------- launcher ----------------
extern "C" void kernel_launch(void* const* d_in, const int* in_sizes, int n_in,
                              void* d_out, int out_size)
{
    const float* raw    = (const float*)d_in[0];
    const float* sp     = (const float*)d_in[1];
    const float* pm_w1  = (const float*)d_in[2];
    const float* pm_b1  = (const float*)d_in[3];
    const float* pm_w3  = (const float*)d_in[4];
    const float* pm_b3  = (const float*)d_in[5];
    const float* pm_wm2 = (const float*)d_in[6];
    const float* pm_bm2 = (const float*)d_in[7];
    const float* sm_w2  = (const float*)d_in[8];
    const float* sm_b2  = (const float*)d_in[9];
    const float* sm_w3  = (const float*)d_in[10];
    const float* sm_b3  = (const float*)d_in[11];
    const float* sm_w5  = (const float*)d_in[12];
    const float* sm_b5  = (const float*)d_in[13];
    const float* sm_w6  = (const float*)d_in[14];
    const float* sm_b6  = (const float*)d_in[15];
    const float* on_w1  = (const float*)d_in[16];
    const float* on_b1  = (const float*)d_in[17];
    const float* on_w2  = (const float*)d_in[18];
    const float* on_b2  = (const float*)d_in[19];

    float* out = (float*)d_out;

    uint32_t *xh, *xl, *w1h, *w1l, *w3h, *w3l, *h1h, *h1l;
    float *partp, *sensp;
    cudaGetSymbolAddress((void**)&xh,  g_xh);
    cudaGetSymbolAddress((void**)&xl,  g_xl);
    cudaGetSymbolAddress((void**)&w1h, g_w1h);
    cudaGetSymbolAddress((void**)&w1l, g_w1l);
    cudaGetSymbolAddress((void**)&w3h, g_w3h);
    cudaGetSymbolAddress((void**)&w3l, g_w3l);
    cudaGetSymbolAddress((void**)&h1h, g_h1h);
    cudaGetSymbolAddress((void**)&h1l, g_h1l);
    cudaGetSymbolAddress((void**)&partp, g_part);
    cudaGetSymbolAddress((void**)&sensp, g_sens);

    const int DYN = 196608 + 1024 + 16384;   // 2x96KB stages + bias + wm2
    cudaFuncSetAttribute(gemm_hmma<3, 0>, cudaFuncAttributeMaxDynamicSharedMemorySize, DYN);
    cudaFuncSetAttribute(gemm_hmma<4, 1>, cudaFuncAttributeMaxDynamicSharedMemorySize, DYN);

    prep_w_kernel<<<(256 * 96 + 512 * 128 + 255) / 256, 256>>>(pm_w1, pm_w3);
    prep_x_kernel<<<BE * 96 / 256, 256>>>(sp);

    // GEMM A: h1 = leaky(x @ w1 + b1)  [BE x 256], K=192 (padded), CTA N=256
    gemm_hmma<3, 0><<<dim3(1, BE / 128), 256, DYN>>>(xh, xl, w1h, w1l, 96, pm_b1, nullptr);
    // GEMM B: fused leaky(h1 @ w3 + b3) @ wm2 -> partials, K=256, CTA N=256
    gemm_hmma<4, 1><<<dim3(2, BE / 128), 256, DYN>>>(h1h, h1l, w3h, w3l, 128, pm_b3, pm_wm2);

    sensor_kernel<<<BATCH / 4, 256>>>(raw, sm_w2, sm_b2, sm_w3, sm_b3,
                                      sm_w5, sm_b5, sm_w6, sm_b6, sensp);
    enkf_kernel<<<BATCH, 256>>>(partp, pm_bm2, sensp, on_w1, on_b1, on_w2, on_b2,
                                out + O1_OFF, out + O2_OFF, out + O3_OFF,
                                out + O4_OFF, out + O5_OFF);
}

// round 8
// speedup vs baseline: 1.2991x; 1.2478x over previous
#include <cuda_runtime.h>
#include <cuda_fp16.h>
#include <cstdint>

#define BATCH 2048
#define ENS   32
#define DX    14
#define DZ    14
#define PM_IN 140
#define SM_IN 220
#define BE    (BATCH * ENS)

#define O1_OFF 0
#define O2_OFF (BATCH * ENS * DX)
#define O3_OFF (O2_OFF + BATCH * DX)
#define O4_OFF (O3_OFF + BATCH * DX)
#define O5_OFF (O4_OFF + BATCH * DZ)

// ---------------- scratch globals (uint32 = packed fp16 pair) ----------------
__device__ uint32_t g_x  [(size_t)BE * 96];    // x   fp16 [BE][192]
__device__ uint32_t g_w1h[256 * 96];           // w1^T hi [256][192]
__device__ uint32_t g_w1l[256 * 96];           // w1^T lo
__device__ uint32_t g_w3h[512 * 128];          // w3^T hi [512][256]
__device__ uint32_t g_w3l[512 * 128];          // w3^T lo
__device__ uint32_t g_h1 [(size_t)BE * 128];   // h1  fp16 [BE][256]
__device__ float    g_part[(size_t)8 * BE * DX];   // 8 partial slices
__device__ float    g_sens[BATCH * DZ];

// ---------------- helpers ----------------
__device__ __forceinline__ uint32_t smem_u32(const void* p) {
    uint32_t a;
    asm("{ .reg .u64 t; cvta.to.shared.u64 t, %1; cvt.u32.u64 %0, t; }" : "=r"(a) : "l"(p));
    return a;
}
#define CP16(d, s) asm volatile("cp.async.cg.shared.global [%0], [%1], 16;" :: "r"(d), "l"(s))
#define CP_COMMIT() asm volatile("cp.async.commit_group;")
#define CP_WAIT0()  asm volatile("cp.async.wait_group 0;" ::: "memory")
#define CP_WAIT1()  asm volatile("cp.async.wait_group 1;" ::: "memory")

__device__ __forceinline__ void ldsm4(uint32_t (&r)[4], uint32_t addr) {
    asm volatile("ldmatrix.sync.aligned.m8n8.x4.shared.b16 {%0,%1,%2,%3}, [%4];"
                 : "=r"(r[0]), "=r"(r[1]), "=r"(r[2]), "=r"(r[3]) : "r"(addr));
}
__device__ __forceinline__ void mma_f16(float (&d)[4], const uint32_t (&a)[4],
                                        uint32_t b0, uint32_t b1) {
    asm volatile(
        "mma.sync.aligned.m16n8k16.row.col.f32.f16.f16.f32 "
        "{%0,%1,%2,%3}, {%4,%5,%6,%7}, {%8,%9}, {%0,%1,%2,%3};"
        : "+f"(d[0]), "+f"(d[1]), "+f"(d[2]), "+f"(d[3])
        : "r"(a[0]), "r"(a[1]), "r"(a[2]), "r"(a[3]), "r"(b0), "r"(b1));
}
__device__ __forceinline__ uint32_t packA2(float v0, float v1) {
    __half h0 = __float2half_rn(v0), h1 = __float2half_rn(v1);
    return (uint32_t)__half_as_ushort(h0) | ((uint32_t)__half_as_ushort(h1) << 16);
}
__device__ __forceinline__ void splitW2(float v0, float v1, uint32_t& hi, uint32_t& lo) {
    __half h0 = __float2half_rn(v0), h1 = __float2half_rn(v1);
    __half g0 = __float2half_rn(v0 - __half2float(h0));
    __half g1 = __float2half_rn(v1 - __half2float(h1));
    hi = (uint32_t)__half_as_ushort(h0) | ((uint32_t)__half_as_ushort(h1) << 16);
    lo = (uint32_t)__half_as_ushort(g0) | ((uint32_t)__half_as_ushort(g1) << 16);
}

// ---------------- prep: x -> fp16, K padded to 192 ----------------
__global__ void __launch_bounds__(256)
prep_x_kernel(const float* __restrict__ x)
{
    int idx = blockIdx.x * 256 + threadIdx.x;   // BE*96
    int row = idx / 96, p = idx % 96, k = 2 * p;
    float v0 = (k < PM_IN) ? x[(size_t)row * PM_IN + k] : 0.f;
    float v1 = (k + 1 < PM_IN) ? x[(size_t)row * PM_IN + k + 1] : 0.f;
    g_x[(size_t)row * 96 + p] = packA2(v0, v1);
}

// ---------------- prep: weights transposed -> fp16 hi/lo ----------------
__global__ void __launch_bounds__(256)
prep_w_kernel(const float* __restrict__ w1, const float* __restrict__ w3)
{
    int idx = blockIdx.x * 256 + threadIdx.x;
    uint32_t hi, lo;
    if (idx < 256 * 96) {                        // w1 [140][256] -> [256][192]
        int n = idx / 96, p = idx % 96, k = 2 * p;
        float v0 = (k < PM_IN) ? w1[(size_t)k * 256 + n] : 0.f;
        float v1 = (k + 1 < PM_IN) ? w1[(size_t)(k + 1) * 256 + n] : 0.f;
        splitW2(v0, v1, hi, lo);
        g_w1h[idx] = hi; g_w1l[idx] = lo;
    } else if (idx < 256 * 96 + 512 * 128) {     // w3 [256][512] -> [512][256]
        int i2 = idx - 256 * 96;
        int n = i2 / 128, p = i2 % 128, k = 2 * p;
        splitW2(w3[(size_t)k * 512 + n], w3[(size_t)(k + 1) * 512 + n], hi, lo);
        g_w3h[i2] = hi; g_w3l[i2] = lo;
    }
}

// ---------------- HMMA fp16 2-product GEMM, double-buffered ---------------
// C-tile 128x128, BK=64, 8 warps (4m x 2n), warp tile 32x64.
// SMEM/stage: A 16KB + Bh 16KB + Bl 16KB = 48KB; 2 stages = 96KB; +bias+wm2.
// EPI=0: h1 = leaky(acc+bias) -> g_h1 (fp16)
// EPI=1: fused wm2 projection -> g_part (8 slices)
template <int KCHUNKS, int EPI>
__global__ void __launch_bounds__(256, 1)
gemm_hmma(const uint32_t* __restrict__ A, const uint32_t* __restrict__ Bh,
          const uint32_t* __restrict__ Bl,
          int kstr,                             // row stride in uint32 (Kpad/2)
          const float* __restrict__ bias, const float* __restrict__ wm2)
{
    extern __shared__ char smem[];
    const uint32_t ub = smem_u32(smem);
    float* biasS = (float*)(smem + 98304);       // 128 floats
    float* wm2s  = (float*)(smem + 99328);       // 128 x 16 floats

    const int tid = threadIdx.x, wid = tid >> 5, lane = tid & 31;
    const int bn = blockIdx.x, bt = blockIdx.y;
    const int mw = (wid >> 1) * 32;              // 4 m-groups
    const int nw = (wid & 1) * 64;               // 2 n-groups

    if (tid < 128) biasS[tid] = bias[bn * 128 + tid];
    if (EPI == 1) {
        for (int i = tid; i < 128 * DX; i += 256) {
            int c = i / DX, m = i % DX;
            wm2s[c * 16 + m] = wm2[(size_t)(bn * 128 + c) * DX + m];
        }
    }

    // 3072 16B units per chunk / 256 threads = 12 per thread
    auto issue_load = [&](int stage, int kc) {
        const uint32_t sb = ub + stage * 49152;
#pragma unroll
        for (int q = 0; q < 12; q++) {
            int i = tid + 256 * q;
            int t = i >> 10, r = (i >> 3) & 127, c = i & 7;
            const uint32_t* gp;
            int grow;
            if (t == 0)      { gp = A;  grow = bt * 128 + r; }
            else if (t == 1) { gp = Bh; grow = bn * 128 + r; }
            else             { gp = Bl; grow = bn * 128 + r; }
            const uint32_t* src = gp + (size_t)grow * kstr + kc * 32 + c * 4;
            uint32_t dst = sb + t * 16384 + r * 128 + ((c * 16) ^ ((r & 7) << 4));
            CP16(dst, src);
        }
        CP_COMMIT();
    };

    float acc[2][8][4];
#pragma unroll
    for (int f = 0; f < 2; f++)
#pragma unroll
        for (int g = 0; g < 8; g++)
#pragma unroll
            for (int e = 0; e < 4; e++) acc[f][g][e] = 0.f;

    issue_load(0, 0);

#pragma unroll 1
    for (int kc = 0; kc < KCHUNKS; kc++) {
        const int s = kc & 1;
        if (kc + 1 < KCHUNKS) {
            issue_load(s ^ 1, kc + 1);
            CP_WAIT1();
        } else {
            CP_WAIT0();
        }
        __syncthreads();

        const uint32_t sb = ub + s * 49152;
#pragma unroll
        for (int k16 = 0; k16 < 4; k16++) {
            uint32_t ah[2][4];
#pragma unroll
            for (int f = 0; f < 2; f++) {
                int mrow = mw + f * 16 + (lane & 15);
                int cb = k16 * 32 + ((lane >> 4) << 4);
                uint32_t off = mrow * 128 + (cb ^ ((mrow & 7) << 4));
                ldsm4(ah[f], sb + off);
            }
            uint32_t bh[4][4], bl[4][4];
#pragma unroll
            for (int g = 0; g < 4; g++) {
                int nrow = nw + g * 16 + ((lane >> 4) << 3) + (lane & 7);
                int cb = k16 * 32 + (((lane >> 3) & 1) << 4);
                uint32_t off = nrow * 128 + (cb ^ ((nrow & 7) << 4));
                ldsm4(bh[g], sb + 16384 + off);
                ldsm4(bl[g], sb + 32768 + off);
            }
#pragma unroll
            for (int f = 0; f < 2; f++)
#pragma unroll
                for (int g = 0; g < 4; g++) {
                    mma_f16(acc[f][2 * g],     ah[f], bh[g][0], bh[g][1]);
                    mma_f16(acc[f][2 * g],     ah[f], bl[g][0], bl[g][1]);
                    mma_f16(acc[f][2 * g + 1], ah[f], bh[g][2], bh[g][3]);
                    mma_f16(acc[f][2 * g + 1], ah[f], bl[g][2], bl[g][3]);
                }
        }
        __syncthreads();
    }

    if (EPI == 0) {
        // h1 = leaky(acc + bias) -> fp16 pairs
#pragma unroll
        for (int f = 0; f < 2; f++) {
            int row0 = bt * 128 + mw + f * 16 + (lane >> 2);
#pragma unroll
            for (int nf = 0; nf < 8; nf++) {
                int col = nw + nf * 8 + 2 * (lane & 3);
                float b0 = biasS[col], b1 = biasS[col + 1];
                float v0 = acc[f][nf][0] + b0, v1 = acc[f][nf][1] + b1;
                float v2 = acc[f][nf][2] + b0, v3 = acc[f][nf][3] + b1;
                v0 = v0 >= 0.f ? v0 : 0.01f * v0;
                v1 = v1 >= 0.f ? v1 : 0.01f * v1;
                v2 = v2 >= 0.f ? v2 : 0.01f * v2;
                v3 = v3 >= 0.f ? v3 : 0.01f * v3;
                int gcol = bn * 128 + col;
                g_h1[(size_t)row0 * 128 + gcol / 2]       = packA2(v0, v1);
                g_h1[(size_t)(row0 + 8) * 128 + gcol / 2] = packA2(v2, v3);
            }
        }
    } else {
        // fused projection: proj[slot][m] = sum_c leaky(acc+b3)[c] * wm2[c][m]
        float proj[4][DX];
#pragma unroll
        for (int s2 = 0; s2 < 4; s2++)
#pragma unroll
            for (int m = 0; m < DX; m++) proj[s2][m] = 0.f;
#pragma unroll
        for (int f = 0; f < 2; f++)
#pragma unroll
            for (int nf = 0; nf < 8; nf++) {
                int col = nw + nf * 8 + 2 * (lane & 3);
#pragma unroll
                for (int e = 0; e < 2; e++) {
                    int c = col + e;
                    float b = biasS[c];
                    float v0 = acc[f][nf][e] + b;
                    float v1 = acc[f][nf][2 + e] + b;
                    v0 = v0 >= 0.f ? v0 : 0.01f * v0;
                    v1 = v1 >= 0.f ? v1 : 0.01f * v1;
                    const float* wr = wm2s + c * 16;
#pragma unroll
                    for (int m = 0; m < DX; m++) {
                        float wv = wr[m];
                        proj[2 * f][m]     += v0 * wv;
                        proj[2 * f + 1][m] += v1 * wv;
                    }
                }
            }
#pragma unroll
        for (int s2 = 0; s2 < 4; s2++)
#pragma unroll
            for (int m = 0; m < DX; m++) {
                proj[s2][m] += __shfl_xor_sync(0xFFFFFFFFu, proj[s2][m], 1);
                proj[s2][m] += __shfl_xor_sync(0xFFFFFFFFu, proj[s2][m], 2);
            }
        if ((lane & 3) == 0) {
            int slice = bn * 2 + (wid & 1);      // 8 slices (bn<4 x 2 n-groups)
#pragma unroll
            for (int s2 = 0; s2 < 4; s2++) {
                int row = bt * 128 + mw + (s2 >> 1) * 16 + (lane >> 2) + (s2 & 1) * 8;
                float* dst = g_part + ((size_t)slice * BE + row) * DX;
#pragma unroll
                for (int m = 0; m < DX; m++) dst[m] = proj[s2][m];
            }
        }
    }
}

// ---------------- sensor MLP on 2048 distinct rows ----------------
__global__ void __launch_bounds__(256)
sensor_kernel(const float* __restrict__ raw,
              const float* __restrict__ w2, const float* __restrict__ b2,
              const float* __restrict__ w3, const float* __restrict__ b3,
              const float* __restrict__ w5, const float* __restrict__ b5,
              const float* __restrict__ w6, const float* __restrict__ b6,
              float* __restrict__ sens)
{
    __shared__ float s[4][SM_IN], h1[4][256], h2[4][256], h3[4][64];
    const int tid = threadIdx.x;
    const int row0 = blockIdx.x * 4;

    for (int i = tid; i < 4 * SM_IN; i += 256)
        s[i / SM_IN][i % SM_IN] = raw[(size_t)(row0 + i / SM_IN) * SM_IN + i % SM_IN];
    __syncthreads();
    {
        float acc[4];
#pragma unroll
        for (int r = 0; r < 4; r++) acc[r] = b2[tid];
        for (int k = 0; k < SM_IN; k++) {
            float w = w2[k * 256 + tid];
#pragma unroll
            for (int r = 0; r < 4; r++) acc[r] += s[r][k] * w;
        }
#pragma unroll
        for (int r = 0; r < 4; r++) h1[r][tid] = acc[r] >= 0.f ? acc[r] : 0.01f * acc[r];
    }
    __syncthreads();
    {
        float acc[4];
#pragma unroll
        for (int r = 0; r < 4; r++) acc[r] = b3[tid];
        for (int k = 0; k < 256; k++) {
            float w = w3[k * 256 + tid];
#pragma unroll
            for (int r = 0; r < 4; r++) acc[r] += h1[r][k] * w;
        }
#pragma unroll
        for (int r = 0; r < 4; r++) h2[r][tid] = acc[r] >= 0.f ? acc[r] : 0.01f * acc[r];
    }
    __syncthreads();
    if (tid < 64) {
        float acc[4];
#pragma unroll
        for (int r = 0; r < 4; r++) acc[r] = b5[tid];
        for (int k = 0; k < 256; k++) {
            float w = w5[k * 64 + tid];
#pragma unroll
            for (int r = 0; r < 4; r++) acc[r] += h2[r][k] * w;
        }
#pragma unroll
        for (int r = 0; r < 4; r++) h3[r][tid] = acc[r] >= 0.f ? acc[r] : 0.01f * acc[r];
    }
    __syncthreads();
    if (tid < DZ) {
        float acc[4];
#pragma unroll
        for (int r = 0; r < 4; r++) acc[r] = b6[tid];
        for (int k = 0; k < 64; k++) {
            float w = w6[k * DZ + tid];
#pragma unroll
            for (int r = 0; r < 4; r++) acc[r] += h3[r][k] * w;
        }
#pragma unroll
        for (int r = 0; r < 4; r++) sens[(size_t)(row0 + r) * DZ + tid] = acc[r];
    }
}

// ---------------- EnKF per batch element ----------------
__global__ void __launch_bounds__(256)
enkf_kernel(const float* __restrict__ part, const float* __restrict__ pm_bm2,
            const float* __restrict__ sens,
            const float* __restrict__ on_w1, const float* __restrict__ on_b1,
            const float* __restrict__ on_w2, const float* __restrict__ on_b2,
            float* __restrict__ out1, float* __restrict__ out2,
            float* __restrict__ out3, float* __restrict__ out4,
            float* __restrict__ out5)
{
    const int b = blockIdx.x, tid = threadIdx.x;
    __shared__ float pred[ENS][DX], ez[ENS][DZ], Am[ENS][DX], corr[ENS][DX];
    __shared__ float sm[DX], zm[DZ], rdiag[DZ], hid[32];
    __shared__ float Mm[DX][DX], Km[DX][DZ], aug[DX][2 * DX], fac[DX];

    for (int i = tid; i < ENS * DX; i += 256) {
        int e = i / DX, j = i % DX;
        size_t row = (size_t)b * ENS + e;
        float p = pm_bm2[j];
#pragma unroll
        for (int q = 0; q < 8; q++) p += part[((size_t)q * BE + row) * DX + j];
        pred[e][j] = p;
    }
    for (int i = tid; i < ENS * DZ; i += 256) {
        int e = i / DZ, j = i % DZ;
        int src = (b * ENS + e) % BATCH;
        float v = sens[src * DZ + j];
        ez[e][j] = v;
        out5[(size_t)(b * ENS + e) * DZ + j] = v;
    }
    __syncthreads();
    if (tid < DX) {
        float s1 = 0.f, s2 = 0.f;
        for (int e = 0; e < ENS; e++) { s1 += pred[e][tid]; s2 += ez[e][tid]; }
        float m1 = s1 * (1.f / ENS), m2 = s2 * (1.f / ENS);
        sm[tid] = m1; zm[tid] = m2;
        out3[b * DX + tid] = m1;
        out4[b * DZ + tid] = m2;
    }
    __syncthreads();
    if (tid < 32) {
        float a = on_b1[tid];
        for (int i = 0; i < DZ; i++) a += zm[i] * on_w1[i * 32 + tid];
        hid[tid] = a > 0.f ? a : 0.f;
    }
    __syncthreads();
    if (tid < DZ) {
        float a = on_b2[tid];
        for (int j = 0; j < 32; j++) a += hid[j] * on_w2[j * DZ + tid];
        a += 0.001f;
        rdiag[tid] = a * a + 0.038729833f;
    }
    for (int i = tid; i < ENS * DX; i += 256)
        Am[i / DX][i % DX] = pred[i / DX][i % DX] - sm[i % DX];
    __syncthreads();
    if (tid < DX * DX) {
        int i = tid / DX, j = tid % DX;
        float s = 0.f;
        for (int e = 0; e < ENS; e++) s += Am[e][i] * Am[e][j];
        float m = s * (1.f / (ENS - 1));
        Mm[i][j] = m;
        aug[i][j] = m + (i == j ? rdiag[i] : 0.f);
        aug[i][DX + j] = (i == j) ? 1.f : 0.f;
    }
    __syncthreads();
    for (int p = 0; p < DX; p++) {
        float pv = aug[p][p];
        __syncthreads();
        if (tid < 2 * DX) aug[p][tid] *= (1.f / pv);
        if (tid < DX) fac[tid] = (tid == p) ? 0.f : aug[tid][p];
        __syncthreads();
        for (int t = tid; t < DX * 2 * DX; t += 256) {
            int rr = t / (2 * DX), c = t % (2 * DX);
            if (rr != p) aug[rr][c] -= fac[rr] * aug[p][c];
        }
        __syncthreads();
    }
    if (tid < DX * DX) {
        int i = tid / DX, j = tid % DX;
        float s = 0.f;
        for (int k = 0; k < DX; k++) s += Mm[i][k] * aug[k][DX + j];
        Km[i][j] = s;
    }
    __syncthreads();
    for (int t = tid; t < ENS * DX; t += 256) {
        int e = t / DX, i = t % DX;
        float s = pred[e][i];
        for (int j = 0; j < DZ; j++) s += Km[i][j] * (ez[e][j] - pred[e][j]);
        corr[e][i] = s;
        out1[(size_t)(b * ENS + e) * DX + i] = s;
    }
    __syncthreads();
    if (tid < DX) {
        float s = 0.f;
        for (int e = 0; e < ENS; e++) s += corr[e][tid];
        out2[b * DX + tid] = s * (1.f / ENS);
    }
}

// ---------------- launcher ----------------
extern "C" void kernel_launch(void* const* d_in, const int* in_sizes, int n_in,
                              void* d_out, int out_size)
{
    const float* raw    = (const float*)d_in[0];
    const float* sp     = (const float*)d_in[1];
    const float* pm_w1  = (const float*)d_in[2];
    const float* pm_b1  = (const float*)d_in[3];
    const float* pm_w3  = (const float*)d_in[4];
    const float* pm_b3  = (const float*)d_in[5];
    const float* pm_wm2 = (const float*)d_in[6];
    const float* pm_bm2 = (const float*)d_in[7];
    const float* sm_w2  = (const float*)d_in[8];
    const float* sm_b2  = (const float*)d_in[9];
    const float* sm_w3  = (const float*)d_in[10];
    const float* sm_b3  = (const float*)d_in[11];
    const float* sm_w5  = (const float*)d_in[12];
    const float* sm_b5  = (const float*)d_in[13];
    const float* sm_w6  = (const float*)d_in[14];
    const float* sm_b6  = (const float*)d_in[15];
    const float* on_w1  = (const float*)d_in[16];
    const float* on_b1  = (const float*)d_in[17];
    const float* on_w2  = (const float*)d_in[18];
    const float* on_b2  = (const float*)d_in[19];

    float* out = (float*)d_out;

    uint32_t *xp, *w1h, *w1l, *w3h, *w3l, *h1p;
    float *partp, *sensp;
    cudaGetSymbolAddress((void**)&xp,  g_x);
    cudaGetSymbolAddress((void**)&w1h, g_w1h);
    cudaGetSymbolAddress((void**)&w1l, g_w1l);
    cudaGetSymbolAddress((void**)&w3h, g_w3h);
    cudaGetSymbolAddress((void**)&w3l, g_w3l);
    cudaGetSymbolAddress((void**)&h1p, g_h1);
    cudaGetSymbolAddress((void**)&partp, g_part);
    cudaGetSymbolAddress((void**)&sensp, g_sens);

    const int DYN = 98304 + 1024 + 8192;   // 2x48KB stages + bias + wm2
    cudaFuncSetAttribute(gemm_hmma<3, 0>, cudaFuncAttributeMaxDynamicSharedMemorySize, DYN);
    cudaFuncSetAttribute(gemm_hmma<4, 1>, cudaFuncAttributeMaxDynamicSharedMemorySize, DYN);

    prep_w_kernel<<<(256 * 96 + 512 * 128 + 255) / 256, 256>>>(pm_w1, pm_w3);
    prep_x_kernel<<<BE * 96 / 256, 256>>>(sp);

    // GEMM A: h1 = leaky(x @ w1 + b1)  [BE x 256], K=192 (padded)
    gemm_hmma<3, 0><<<dim3(2, BE / 128), 256, DYN>>>(xp, w1h, w1l, 96, pm_b1, nullptr);
    // GEMM B: fused leaky(h1 @ w3 + b3) @ wm2 -> partials, K=256
    gemm_hmma<4, 1><<<dim3(4, BE / 128), 256, DYN>>>(h1p, w3h, w3l, 128, pm_b3, pm_wm2);

    sensor_kernel<<<BATCH / 4, 256>>>(raw, sm_w2, sm_b2, sm_w3, sm_b3,
                                      sm_w5, sm_b5, sm_w6, sm_b6, sensp);
    enkf_kernel<<<BATCH, 256>>>(partp, pm_bm2, sensp, on_w1, on_b1, on_w2, on_b2,
                                out + O1_OFF, out + O2_OFF, out + O3_OFF,
                                out + O4_OFF, out + O5_OFF);
}

// round 9
// speedup vs baseline: 1.5182x; 1.1687x over previous
#include <cuda_runtime.h>
#include <cuda_fp16.h>
#include <cstdint>

#define BATCH 2048
#define ENS   32
#define DX    14
#define DZ    14
#define PM_IN 140
#define SM_IN 220
#define BE    (BATCH * ENS)

#define O1_OFF 0
#define O2_OFF (BATCH * ENS * DX)
#define O3_OFF (O2_OFF + BATCH * DX)
#define O4_OFF (O3_OFF + BATCH * DX)
#define O5_OFF (O4_OFF + BATCH * DZ)

// ---------------- scratch globals (uint32 = packed fp16 pair) ----------------
__device__ uint32_t g_x [(size_t)BE * 96];     // x   fp16 [BE][192]
__device__ uint32_t g_w1[256 * 96];            // w1^T fp16 [256][192]
__device__ uint32_t g_w3[512 * 128];           // w3^T fp16 [512][256]
__device__ uint32_t g_h1[(size_t)BE * 128];    // h1  fp16 [BE][256]
__device__ float    g_part[(size_t)8 * BE * DX];   // 8 partial slices
__device__ float    g_sens[BATCH * DZ];

// ---------------- helpers ----------------
__device__ __forceinline__ uint32_t smem_u32(const void* p) {
    uint32_t a;
    asm("{ .reg .u64 t; cvta.to.shared.u64 t, %1; cvt.u32.u64 %0, t; }" : "=r"(a) : "l"(p));
    return a;
}
#define CP16(d, s) asm volatile("cp.async.cg.shared.global [%0], [%1], 16;" :: "r"(d), "l"(s))
#define CP_COMMIT() asm volatile("cp.async.commit_group;")
#define CP_WAIT0()  asm volatile("cp.async.wait_group 0;" ::: "memory")
#define CP_WAIT1()  asm volatile("cp.async.wait_group 1;" ::: "memory")

__device__ __forceinline__ void ldsm4(uint32_t (&r)[4], uint32_t addr) {
    asm volatile("ldmatrix.sync.aligned.m8n8.x4.shared.b16 {%0,%1,%2,%3}, [%4];"
                 : "=r"(r[0]), "=r"(r[1]), "=r"(r[2]), "=r"(r[3]) : "r"(addr));
}
__device__ __forceinline__ void mma_f16(float (&d)[4], const uint32_t (&a)[4],
                                        uint32_t b0, uint32_t b1) {
    asm volatile(
        "mma.sync.aligned.m16n8k16.row.col.f32.f16.f16.f32 "
        "{%0,%1,%2,%3}, {%4,%5,%6,%7}, {%8,%9}, {%0,%1,%2,%3};"
        : "+f"(d[0]), "+f"(d[1]), "+f"(d[2]), "+f"(d[3])
        : "r"(a[0]), "r"(a[1]), "r"(a[2]), "r"(a[3]), "r"(b0), "r"(b1));
}
__device__ __forceinline__ uint32_t packA2(float v0, float v1) {
    __half h0 = __float2half_rn(v0), h1 = __float2half_rn(v1);
    return (uint32_t)__half_as_ushort(h0) | ((uint32_t)__half_as_ushort(h1) << 16);
}

// ---------------- prep: x -> fp16, K padded to 192 ----------------
__global__ void __launch_bounds__(256)
prep_x_kernel(const float* __restrict__ x)
{
    int idx = blockIdx.x * 256 + threadIdx.x;   // BE*96
    int row = idx / 96, p = idx % 96, k = 2 * p;
    float v0 = (k < PM_IN) ? x[(size_t)row * PM_IN + k] : 0.f;
    float v1 = (k + 1 < PM_IN) ? x[(size_t)row * PM_IN + k + 1] : 0.f;
    g_x[(size_t)row * 96 + p] = packA2(v0, v1);
}

// ---------------- prep: weights transposed -> fp16 ----------------
__global__ void __launch_bounds__(256)
prep_w_kernel(const float* __restrict__ w1, const float* __restrict__ w3)
{
    int idx = blockIdx.x * 256 + threadIdx.x;
    if (idx < 256 * 96) {                        // w1 [140][256] -> [256][192]
        int n = idx / 96, p = idx % 96, k = 2 * p;
        float v0 = (k < PM_IN) ? w1[(size_t)k * 256 + n] : 0.f;
        float v1 = (k + 1 < PM_IN) ? w1[(size_t)(k + 1) * 256 + n] : 0.f;
        g_w1[idx] = packA2(v0, v1);
    } else if (idx < 256 * 96 + 512 * 128) {     // w3 [256][512] -> [512][256]
        int i2 = idx - 256 * 96;
        int n = i2 / 128, p = i2 % 128, k = 2 * p;
        g_w3[i2] = packA2(w3[(size_t)k * 512 + n], w3[(size_t)(k + 1) * 512 + n]);
    }
}

// ---------------- HMMA fp16 1-product GEMM, 16 warps ----------------------
// CTA tile 128x256, BK=64, 16 warps (4m x 4n), warp tile 32x64.
// SMEM/stage: A 16KB + B 32KB = 48KB; 2 stages = 96KB; + bias(1KB) + wm2(16KB).
// EPI=0: h1 = leaky(acc+bias) -> g_h1 (fp16)
// EPI=1: fused wm2 projection -> g_part (8 slices)
template <int KCHUNKS, int EPI>
__global__ void __launch_bounds__(512, 1)
gemm_hmma(const uint32_t* __restrict__ A, const uint32_t* __restrict__ B,
          int kstr,                             // row stride in uint32 (Kpad/2)
          const float* __restrict__ bias, const float* __restrict__ wm2)
{
    extern __shared__ char smem[];
    const uint32_t ub = smem_u32(smem);
    float* biasS = (float*)(smem + 98304);       // 256 floats
    float* wm2s  = (float*)(smem + 99328);       // 256 x 16 floats

    const int tid = threadIdx.x, wid = tid >> 5, lane = tid & 31;
    const int bn = blockIdx.x, bt = blockIdx.y;
    const int mw = (wid >> 2) * 32;              // 4 m-groups
    const int nw = (wid & 3) * 64;               // 4 n-groups

    if (tid < 256) biasS[tid] = bias[bn * 256 + tid];
    if (EPI == 1) {
        for (int i = tid; i < 256 * DX; i += 512) {
            int c = i / DX, m = i % DX;
            wm2s[c * 16 + m] = wm2[(size_t)(bn * 256 + c) * DX + m];
        }
    }

    // 3072 16B units per chunk / 512 threads = 6 per thread
    auto issue_load = [&](int stage, int kc) {
        const uint32_t sb = ub + stage * 49152;
#pragma unroll
        for (int q = 0; q < 6; q++) {
            int i = tid + 512 * q;
            if (i < 1024) {                      // A tile: 128 rows
                int r = i >> 3, c = i & 7;
                const uint32_t* src = A + (size_t)(bt * 128 + r) * kstr + kc * 32 + c * 4;
                uint32_t dst = sb + r * 128 + ((c * 16) ^ ((r & 7) << 4));
                CP16(dst, src);
            } else {                             // B tile: 256 rows
                int j = i - 1024;
                int r = j >> 3, c = j & 7;
                const uint32_t* src = B + (size_t)(bn * 256 + r) * kstr + kc * 32 + c * 4;
                uint32_t dst = sb + 16384 + r * 128 + ((c * 16) ^ ((r & 7) << 4));
                CP16(dst, src);
            }
        }
        CP_COMMIT();
    };

    float acc[2][8][4];
#pragma unroll
    for (int f = 0; f < 2; f++)
#pragma unroll
        for (int g = 0; g < 8; g++)
#pragma unroll
            for (int e = 0; e < 4; e++) acc[f][g][e] = 0.f;

    issue_load(0, 0);

#pragma unroll 1
    for (int kc = 0; kc < KCHUNKS; kc++) {
        const int s = kc & 1;
        if (kc + 1 < KCHUNKS) {
            issue_load(s ^ 1, kc + 1);
            CP_WAIT1();
        } else {
            CP_WAIT0();
        }
        __syncthreads();

        const uint32_t sb = ub + s * 49152;
#pragma unroll
        for (int k16 = 0; k16 < 4; k16++) {
            uint32_t ah[2][4];
#pragma unroll
            for (int f = 0; f < 2; f++) {
                int mrow = mw + f * 16 + (lane & 15);
                int cb = k16 * 32 + ((lane >> 4) << 4);
                uint32_t off = mrow * 128 + (cb ^ ((mrow & 7) << 4));
                ldsm4(ah[f], sb + off);
            }
            uint32_t bh[4][4];
#pragma unroll
            for (int g = 0; g < 4; g++) {
                int nrow = nw + g * 16 + ((lane >> 4) << 3) + (lane & 7);
                int cb = k16 * 32 + (((lane >> 3) & 1) << 4);
                uint32_t off = nrow * 128 + (cb ^ ((nrow & 7) << 4));
                ldsm4(bh[g], sb + 16384 + off);
            }
#pragma unroll
            for (int f = 0; f < 2; f++)
#pragma unroll
                for (int g = 0; g < 4; g++) {
                    mma_f16(acc[f][2 * g],     ah[f], bh[g][0], bh[g][1]);
                    mma_f16(acc[f][2 * g + 1], ah[f], bh[g][2], bh[g][3]);
                }
        }
        __syncthreads();
    }

    if (EPI == 0) {
        // h1 = leaky(acc + bias) -> fp16 pairs
#pragma unroll
        for (int f = 0; f < 2; f++) {
            int row0 = bt * 128 + mw + f * 16 + (lane >> 2);
#pragma unroll
            for (int nf = 0; nf < 8; nf++) {
                int col = nw + nf * 8 + 2 * (lane & 3);
                float b0 = biasS[col], b1 = biasS[col + 1];
                float v0 = acc[f][nf][0] + b0, v1 = acc[f][nf][1] + b1;
                float v2 = acc[f][nf][2] + b0, v3 = acc[f][nf][3] + b1;
                v0 = v0 >= 0.f ? v0 : 0.01f * v0;
                v1 = v1 >= 0.f ? v1 : 0.01f * v1;
                v2 = v2 >= 0.f ? v2 : 0.01f * v2;
                v3 = v3 >= 0.f ? v3 : 0.01f * v3;
                int gcol = bn * 256 + col;
                g_h1[(size_t)row0 * 128 + gcol / 2]       = packA2(v0, v1);
                g_h1[(size_t)(row0 + 8) * 128 + gcol / 2] = packA2(v2, v3);
            }
        }
    } else {
        // fused projection: proj[slot][m] = sum_c leaky(acc+b3)[c] * wm2[c][m]
        float proj[4][DX];
#pragma unroll
        for (int s2 = 0; s2 < 4; s2++)
#pragma unroll
            for (int m = 0; m < DX; m++) proj[s2][m] = 0.f;
#pragma unroll
        for (int f = 0; f < 2; f++)
#pragma unroll
            for (int nf = 0; nf < 8; nf++) {
                int col = nw + nf * 8 + 2 * (lane & 3);
#pragma unroll
                for (int e = 0; e < 2; e++) {
                    int c = col + e;
                    float b = biasS[c];
                    float v0 = acc[f][nf][e] + b;
                    float v1 = acc[f][nf][2 + e] + b;
                    v0 = v0 >= 0.f ? v0 : 0.01f * v0;
                    v1 = v1 >= 0.f ? v1 : 0.01f * v1;
                    const float* wr = wm2s + c * 16;
#pragma unroll
                    for (int m = 0; m < DX; m++) {
                        float wv = wr[m];
                        proj[2 * f][m]     += v0 * wv;
                        proj[2 * f + 1][m] += v1 * wv;
                    }
                }
            }
#pragma unroll
        for (int s2 = 0; s2 < 4; s2++)
#pragma unroll
            for (int m = 0; m < DX; m++) {
                proj[s2][m] += __shfl_xor_sync(0xFFFFFFFFu, proj[s2][m], 1);
                proj[s2][m] += __shfl_xor_sync(0xFFFFFFFFu, proj[s2][m], 2);
            }
        if ((lane & 3) == 0) {
            int slice = bn * 4 + (wid & 3);      // 8 slices (bn<2 x 4 n-groups)
#pragma unroll
            for (int s2 = 0; s2 < 4; s2++) {
                int row = bt * 128 + mw + (s2 >> 1) * 16 + (lane >> 2) + (s2 & 1) * 8;
                float* dst = g_part + ((size_t)slice * BE + row) * DX;
#pragma unroll
                for (int m = 0; m < DX; m++) dst[m] = proj[s2][m];
            }
        }
    }
}

// ---------------- sensor MLP on 2048 distinct rows ----------------
__global__ void __launch_bounds__(256)
sensor_kernel(const float* __restrict__ raw,
              const float* __restrict__ w2, const float* __restrict__ b2,
              const float* __restrict__ w3, const float* __restrict__ b3,
              const float* __restrict__ w5, const float* __restrict__ b5,
              const float* __restrict__ w6, const float* __restrict__ b6,
              float* __restrict__ sens)
{
    __shared__ float s[4][SM_IN], h1[4][256], h2[4][256], h3[4][64];
    const int tid = threadIdx.x;
    const int row0 = blockIdx.x * 4;

    for (int i = tid; i < 4 * SM_IN; i += 256)
        s[i / SM_IN][i % SM_IN] = raw[(size_t)(row0 + i / SM_IN) * SM_IN + i % SM_IN];
    __syncthreads();
    {
        float acc[4];
#pragma unroll
        for (int r = 0; r < 4; r++) acc[r] = b2[tid];
        for (int k = 0; k < SM_IN; k++) {
            float w = w2[k * 256 + tid];
#pragma unroll
            for (int r = 0; r < 4; r++) acc[r] += s[r][k] * w;
        }
#pragma unroll
        for (int r = 0; r < 4; r++) h1[r][tid] = acc[r] >= 0.f ? acc[r] : 0.01f * acc[r];
    }
    __syncthreads();
    {
        float acc[4];
#pragma unroll
        for (int r = 0; r < 4; r++) acc[r] = b3[tid];
        for (int k = 0; k < 256; k++) {
            float w = w3[k * 256 + tid];
#pragma unroll
            for (int r = 0; r < 4; r++) acc[r] += h1[r][k] * w;
        }
#pragma unroll
        for (int r = 0; r < 4; r++) h2[r][tid] = acc[r] >= 0.f ? acc[r] : 0.01f * acc[r];
    }
    __syncthreads();
    if (tid < 64) {
        float acc[4];
#pragma unroll
        for (int r = 0; r < 4; r++) acc[r] = b5[tid];
        for (int k = 0; k < 256; k++) {
            float w = w5[k * 64 + tid];
#pragma unroll
            for (int r = 0; r < 4; r++) acc[r] += h2[r][k] * w;
        }
#pragma unroll
        for (int r = 0; r < 4; r++) h3[r][tid] = acc[r] >= 0.f ? acc[r] : 0.01f * acc[r];
    }
    __syncthreads();
    if (tid < DZ) {
        float acc[4];
#pragma unroll
        for (int r = 0; r < 4; r++) acc[r] = b6[tid];
        for (int k = 0; k < 64; k++) {
            float w = w6[k * DZ + tid];
#pragma unroll
            for (int r = 0; r < 4; r++) acc[r] += h3[r][k] * w;
        }
#pragma unroll
        for (int r = 0; r < 4; r++) sens[(size_t)(row0 + r) * DZ + tid] = acc[r];
    }
}

// ---------------- EnKF per batch element ----------------
__global__ void __launch_bounds__(256)
enkf_kernel(const float* __restrict__ part, const float* __restrict__ pm_bm2,
            const float* __restrict__ sens,
            const float* __restrict__ on_w1, const float* __restrict__ on_b1,
            const float* __restrict__ on_w2, const float* __restrict__ on_b2,
            float* __restrict__ out1, float* __restrict__ out2,
            float* __restrict__ out3, float* __restrict__ out4,
            float* __restrict__ out5)
{
    const int b = blockIdx.x, tid = threadIdx.x;
    __shared__ float pred[ENS][DX], ez[ENS][DZ], Am[ENS][DX], corr[ENS][DX];
    __shared__ float sm[DX], zm[DZ], rdiag[DZ], hid[32];
    __shared__ float Mm[DX][DX], Km[DX][DZ], aug[DX][2 * DX], fac[DX];

    for (int i = tid; i < ENS * DX; i += 256) {
        int e = i / DX, j = i % DX;
        size_t row = (size_t)b * ENS + e;
        float p = pm_bm2[j];
#pragma unroll
        for (int q = 0; q < 8; q++) p += part[((size_t)q * BE + row) * DX + j];
        pred[e][j] = p;
    }
    for (int i = tid; i < ENS * DZ; i += 256) {
        int e = i / DZ, j = i % DZ;
        int src = (b * ENS + e) % BATCH;
        float v = sens[src * DZ + j];
        ez[e][j] = v;
        out5[(size_t)(b * ENS + e) * DZ + j] = v;
    }
    __syncthreads();
    if (tid < DX) {
        float s1 = 0.f, s2 = 0.f;
        for (int e = 0; e < ENS; e++) { s1 += pred[e][tid]; s2 += ez[e][tid]; }
        float m1 = s1 * (1.f / ENS), m2 = s2 * (1.f / ENS);
        sm[tid] = m1; zm[tid] = m2;
        out3[b * DX + tid] = m1;
        out4[b * DZ + tid] = m2;
    }
    __syncthreads();
    if (tid < 32) {
        float a = on_b1[tid];
        for (int i = 0; i < DZ; i++) a += zm[i] * on_w1[i * 32 + tid];
        hid[tid] = a > 0.f ? a : 0.f;
    }
    __syncthreads();
    if (tid < DZ) {
        float a = on_b2[tid];
        for (int j = 0; j < 32; j++) a += hid[j] * on_w2[j * DZ + tid];
        a += 0.001f;
        rdiag[tid] = a * a + 0.038729833f;
    }
    for (int i = tid; i < ENS * DX; i += 256)
        Am[i / DX][i % DX] = pred[i / DX][i % DX] - sm[i % DX];
    __syncthreads();
    if (tid < DX * DX) {
        int i = tid / DX, j = tid % DX;
        float s = 0.f;
        for (int e = 0; e < ENS; e++) s += Am[e][i] * Am[e][j];
        float m = s * (1.f / (ENS - 1));
        Mm[i][j] = m;
        aug[i][j] = m + (i == j ? rdiag[i] : 0.f);
        aug[i][DX + j] = (i == j) ? 1.f : 0.f;
    }
    __syncthreads();
    for (int p = 0; p < DX; p++) {
        float pv = aug[p][p];
        __syncthreads();
        if (tid < 2 * DX) aug[p][tid] *= (1.f / pv);
        if (tid < DX) fac[tid] = (tid == p) ? 0.f : aug[tid][p];
        __syncthreads();
        for (int t = tid; t < DX * 2 * DX; t += 256) {
            int rr = t / (2 * DX), c = t % (2 * DX);
            if (rr != p) aug[rr][c] -= fac[rr] * aug[p][c];
        }
        __syncthreads();
    }
    if (tid < DX * DX) {
        int i = tid / DX, j = tid % DX;
        float s = 0.f;
        for (int k = 0; k < DX; k++) s += Mm[i][k] * aug[k][DX + j];
        Km[i][j] = s;
    }
    __syncthreads();
    for (int t = tid; t < ENS * DX; t += 256) {
        int e = t / DX, i = t % DX;
        float s = pred[e][i];
        for (int j = 0; j < DZ; j++) s += Km[i][j] * (ez[e][j] - pred[e][j]);
        corr[e][i] = s;
        out1[(size_t)(b * ENS + e) * DX + i] = s;
    }
    __syncthreads();
    if (tid < DX) {
        float s = 0.f;
        for (int e = 0; e < ENS; e++) s += corr[e][tid];
        out2[b * DX + tid] = s * (1.f / ENS);
    }
}

// ---------------- launcher ----------------
extern "C" void kernel_launch(void* const* d_in, const int* in_sizes, int n_in,
                              void* d_out, int out_size)
{
    const float* raw    = (const float*)d_in[0];
    const float* sp     = (const float*)d_in[1];
    const float* pm_w1  = (const float*)d_in[2];
    const float* pm_b1  = (const float*)d_in[3];
    const float* pm_w3  = (const float*)d_in[4];
    const float* pm_b3  = (const float*)d_in[5];
    const float* pm_wm2 = (const float*)d_in[6];
    const float* pm_bm2 = (const float*)d_in[7];
    const float* sm_w2  = (const float*)d_in[8];
    const float* sm_b2  = (const float*)d_in[9];
    const float* sm_w3  = (const float*)d_in[10];
    const float* sm_b3  = (const float*)d_in[11];
    const float* sm_w5  = (const float*)d_in[12];
    const float* sm_b5  = (const float*)d_in[13];
    const float* sm_w6  = (const float*)d_in[14];
    const float* sm_b6  = (const float*)d_in[15];
    const float* on_w1  = (const float*)d_in[16];
    const float* on_b1  = (const float*)d_in[17];
    const float* on_w2  = (const float*)d_in[18];
    const float* on_b2  = (const float*)d_in[19];

    float* out = (float*)d_out;

    uint32_t *xp, *w1p, *w3p, *h1p;
    float *partp, *sensp;
    cudaGetSymbolAddress((void**)&xp,  g_x);
    cudaGetSymbolAddress((void**)&w1p, g_w1);
    cudaGetSymbolAddress((void**)&w3p, g_w3);
    cudaGetSymbolAddress((void**)&h1p, g_h1);
    cudaGetSymbolAddress((void**)&partp, g_part);
    cudaGetSymbolAddress((void**)&sensp, g_sens);

    const int DYN = 98304 + 1024 + 16384;   // 2x48KB stages + bias + wm2
    cudaFuncSetAttribute(gemm_hmma<3, 0>, cudaFuncAttributeMaxDynamicSharedMemorySize, DYN);
    cudaFuncSetAttribute(gemm_hmma<4, 1>, cudaFuncAttributeMaxDynamicSharedMemorySize, DYN);

    prep_w_kernel<<<(256 * 96 + 512 * 128 + 255) / 256, 256>>>(pm_w1, pm_w3);
    prep_x_kernel<<<BE * 96 / 256, 256>>>(sp);

    // GEMM A: h1 = leaky(x @ w1 + b1)  [BE x 256], K=192 (padded), CTA N=256
    gemm_hmma<3, 0><<<dim3(1, BE / 128), 512, DYN>>>(xp, w1p, 96, pm_b1, nullptr);
    // GEMM B: fused leaky(h1 @ w3 + b3) @ wm2 -> partials, K=256, CTA N=256
    gemm_hmma<4, 1><<<dim3(2, BE / 128), 512, DYN>>>(h1p, w3p, 128, pm_b3, pm_wm2);

    sensor_kernel<<<BATCH / 4, 256>>>(raw, sm_w2, sm_b2, sm_w3, sm_b3,
                                      sm_w5, sm_b5, sm_w6, sm_b6, sensp);
    enkf_kernel<<<BATCH, 256>>>(partp, pm_bm2, sensp, on_w1, on_b1, on_w2, on_b2,
                                out + O1_OFF, out + O2_OFF, out + O3_OFF,
                                out + O4_OFF, out + O5_OFF);
}

// round 10
// speedup vs baseline: 1.6664x; 1.0976x over previous
#include <cuda_runtime.h>
#include <cuda_fp16.h>
#include <cstdint>

#define BATCH 2048
#define ENS   32
#define DX    14
#define DZ    14
#define PM_IN 140
#define SM_IN 220
#define BE    (BATCH * ENS)

#define O1_OFF 0
#define O2_OFF (BATCH * ENS * DX)
#define O3_OFF (O2_OFF + BATCH * DX)
#define O4_OFF (O3_OFF + BATCH * DX)
#define O5_OFF (O4_OFF + BATCH * DZ)

// smem layout (per CTA): 3 stages x 32KB tiles, then bias, then wm2 slice
#define STAGE_BYTES 32768
#define BIAS_OFF    98304
#define WM2_OFF     98816
#define DYN_SMEM    107008

// ---------------- scratch globals (uint32 = packed fp16 pair) ----------------
__device__ uint32_t g_x [(size_t)BE * 96];     // x   fp16 [BE][192]
__device__ uint32_t g_w1[256 * 96];            // w1^T fp16 [256][192]
__device__ uint32_t g_w3[512 * 128];           // w3^T fp16 [512][256]
__device__ uint32_t g_h1[(size_t)BE * 128];    // h1  fp16 [BE][256]
__device__ float    g_part[(size_t)8 * BE * DX];   // 8 partial slices
__device__ float    g_sens[BATCH * DZ];

// ---------------- helpers ----------------
__device__ __forceinline__ uint32_t smem_u32(const void* p) {
    uint32_t a;
    asm("{ .reg .u64 t; cvta.to.shared.u64 t, %1; cvt.u32.u64 %0, t; }" : "=r"(a) : "l"(p));
    return a;
}
#define CP16(d, s) asm volatile("cp.async.cg.shared.global [%0], [%1], 16;" :: "r"(d), "l"(s))
#define CP_COMMIT() asm volatile("cp.async.commit_group;")
#define CP_WAITG(n) asm volatile("cp.async.wait_group %0;" :: "n"(n) : "memory")

__device__ __forceinline__ void ldsm4(uint32_t (&r)[4], uint32_t addr) {
    asm volatile("ldmatrix.sync.aligned.m8n8.x4.shared.b16 {%0,%1,%2,%3}, [%4];"
                 : "=r"(r[0]), "=r"(r[1]), "=r"(r[2]), "=r"(r[3]) : "r"(addr));
}
__device__ __forceinline__ void mma_f16(float (&d)[4], const uint32_t (&a)[4],
                                        uint32_t b0, uint32_t b1) {
    asm volatile(
        "mma.sync.aligned.m16n8k16.row.col.f32.f16.f16.f32 "
        "{%0,%1,%2,%3}, {%4,%5,%6,%7}, {%8,%9}, {%0,%1,%2,%3};"
        : "+f"(d[0]), "+f"(d[1]), "+f"(d[2]), "+f"(d[3])
        : "r"(a[0]), "r"(a[1]), "r"(a[2]), "r"(a[3]), "r"(b0), "r"(b1));
}
__device__ __forceinline__ uint32_t packA2(float v0, float v1) {
    __half h0 = __float2half_rn(v0), h1 = __float2half_rn(v1);
    return (uint32_t)__half_as_ushort(h0) | ((uint32_t)__half_as_ushort(h1) << 16);
}

// ---------------- prep: x -> fp16, K padded to 192 ----------------
__global__ void __launch_bounds__(256)
prep_x_kernel(const float* __restrict__ x)
{
    int idx = blockIdx.x * 256 + threadIdx.x;   // BE*96
    int row = idx / 96, p = idx % 96, k = 2 * p;
    float v0 = (k < PM_IN) ? x[(size_t)row * PM_IN + k] : 0.f;
    float v1 = (k + 1 < PM_IN) ? x[(size_t)row * PM_IN + k + 1] : 0.f;
    g_x[(size_t)row * 96 + p] = packA2(v0, v1);
}

// ---------------- prep: weights transposed -> fp16 ----------------
__global__ void __launch_bounds__(256)
prep_w_kernel(const float* __restrict__ w1, const float* __restrict__ w3)
{
    int idx = blockIdx.x * 256 + threadIdx.x;
    if (idx < 256 * 96) {                        // w1 [140][256] -> [256][192]
        int n = idx / 96, p = idx % 96, k = 2 * p;
        float v0 = (k < PM_IN) ? w1[(size_t)k * 256 + n] : 0.f;
        float v1 = (k + 1 < PM_IN) ? w1[(size_t)(k + 1) * 256 + n] : 0.f;
        g_w1[idx] = packA2(v0, v1);
    } else if (idx < 256 * 96 + 512 * 128) {     // w3 [256][512] -> [512][256]
        int i2 = idx - 256 * 96;
        int n = i2 / 128, p = i2 % 128, k = 2 * p;
        g_w3[i2] = packA2(w3[(size_t)k * 512 + n], w3[(size_t)(k + 1) * 512 + n]);
    }
}

// ---------------- HMMA fp16 GEMM: 8 warps, 2 CTAs/SM, 3-stage pipeline -----
// CTA tile 128x128, BK=64, 8 warps (4m x 2n), warp tile 32x64.
// SMEM/stage: A 16KB + B 16KB = 32KB; 3 stages; + bias(512B) + wm2(8KB).
// EPI=0: h1 = leaky(acc+bias) -> g_h1 (fp16)
// EPI=1: fused wm2 projection -> g_part (8 slices)
template <int KCHUNKS, int EPI>
__global__ void __launch_bounds__(256, 2)
gemm_hmma(const uint32_t* __restrict__ A, const uint32_t* __restrict__ B,
          int kstr,                             // row stride in uint32 (Kpad/2)
          const float* __restrict__ bias, const float* __restrict__ wm2)
{
    extern __shared__ char smem[];
    const uint32_t ub = smem_u32(smem);
    float* biasS = (float*)(smem + BIAS_OFF);
    float* wm2s  = (float*)(smem + WM2_OFF);

    const int tid = threadIdx.x, wid = tid >> 5, lane = tid & 31;
    const int bn = blockIdx.x, bt = blockIdx.y;
    const int mw = (wid >> 1) * 32;              // 4 m-groups
    const int nw = (wid & 1) * 64;               // 2 n-groups

    if (tid < 128) biasS[tid] = bias[bn * 128 + tid];
    if (EPI == 1) {
        for (int i = tid; i < 128 * DX; i += 256) {
            int c = i / DX, m = i % DX;
            wm2s[c * 16 + m] = wm2[(size_t)(bn * 128 + c) * DX + m];
        }
    }

    // 2048 16B units per chunk / 256 threads = 8 per thread
    auto issue_load = [&](int stage, int kc) {
        const uint32_t sb = ub + stage * STAGE_BYTES;
#pragma unroll
        for (int q = 0; q < 8; q++) {
            int i = tid + 256 * q;
            int t = i >> 10, r = (i >> 3) & 127, c = i & 7;
            const uint32_t* gp = t ? B : A;
            int grow = (t ? bn : bt) * 128 + r;
            const uint32_t* src = gp + (size_t)grow * kstr + kc * 32 + c * 4;
            uint32_t dst = sb + t * 16384 + r * 128 + ((c * 16) ^ ((r & 7) << 4));
            CP16(dst, src);
        }
        CP_COMMIT();
    };

    float acc[2][8][4];
#pragma unroll
    for (int f = 0; f < 2; f++)
#pragma unroll
        for (int g = 0; g < 8; g++)
#pragma unroll
            for (int e = 0; e < 4; e++) acc[f][g][e] = 0.f;

    issue_load(0, 0);
    if (KCHUNKS > 1) issue_load(1, 1);

#pragma unroll 1
    for (int kc = 0; kc < KCHUNKS; kc++) {
        if (kc + 2 < KCHUNKS) {
            issue_load((kc + 2) % 3, kc + 2);
            CP_WAITG(2);
        } else if (kc + 1 < KCHUNKS) {
            CP_WAITG(1);
        } else {
            CP_WAITG(0);
        }
        __syncthreads();

        const uint32_t sb = ub + (kc % 3) * STAGE_BYTES;
#pragma unroll
        for (int k16 = 0; k16 < 4; k16++) {
            uint32_t ah[2][4];
#pragma unroll
            for (int f = 0; f < 2; f++) {
                int mrow = mw + f * 16 + (lane & 15);
                int cb = k16 * 32 + ((lane >> 4) << 4);
                uint32_t off = mrow * 128 + (cb ^ ((mrow & 7) << 4));
                ldsm4(ah[f], sb + off);
            }
            uint32_t bh[4][4];
#pragma unroll
            for (int g = 0; g < 4; g++) {
                int nrow = nw + g * 16 + ((lane >> 4) << 3) + (lane & 7);
                int cb = k16 * 32 + (((lane >> 3) & 1) << 4);
                uint32_t off = nrow * 128 + (cb ^ ((nrow & 7) << 4));
                ldsm4(bh[g], sb + 16384 + off);
            }
#pragma unroll
            for (int f = 0; f < 2; f++)
#pragma unroll
                for (int g = 0; g < 4; g++) {
                    mma_f16(acc[f][2 * g],     ah[f], bh[g][0], bh[g][1]);
                    mma_f16(acc[f][2 * g + 1], ah[f], bh[g][2], bh[g][3]);
                }
        }
        __syncthreads();
    }

    if (EPI == 0) {
        // h1 = leaky(acc + bias) -> fp16 pairs
#pragma unroll
        for (int f = 0; f < 2; f++) {
            int row0 = bt * 128 + mw + f * 16 + (lane >> 2);
#pragma unroll
            for (int nf = 0; nf < 8; nf++) {
                int col = nw + nf * 8 + 2 * (lane & 3);
                float b0 = biasS[col], b1 = biasS[col + 1];
                float v0 = acc[f][nf][0] + b0, v1 = acc[f][nf][1] + b1;
                float v2 = acc[f][nf][2] + b0, v3 = acc[f][nf][3] + b1;
                v0 = v0 >= 0.f ? v0 : 0.01f * v0;
                v1 = v1 >= 0.f ? v1 : 0.01f * v1;
                v2 = v2 >= 0.f ? v2 : 0.01f * v2;
                v3 = v3 >= 0.f ? v3 : 0.01f * v3;
                int gcol = bn * 128 + col;
                g_h1[(size_t)row0 * 128 + gcol / 2]       = packA2(v0, v1);
                g_h1[(size_t)(row0 + 8) * 128 + gcol / 2] = packA2(v2, v3);
            }
        }
    } else {
        // fused projection: proj[slot][m] = sum_c leaky(acc+b3)[c] * wm2[c][m]
        float proj[4][DX];
#pragma unroll
        for (int s2 = 0; s2 < 4; s2++)
#pragma unroll
            for (int m = 0; m < DX; m++) proj[s2][m] = 0.f;
#pragma unroll
        for (int f = 0; f < 2; f++)
#pragma unroll
            for (int nf = 0; nf < 8; nf++) {
                int col = nw + nf * 8 + 2 * (lane & 3);
#pragma unroll
                for (int e = 0; e < 2; e++) {
                    int c = col + e;
                    float b = biasS[c];
                    float v0 = acc[f][nf][e] + b;
                    float v1 = acc[f][nf][2 + e] + b;
                    v0 = v0 >= 0.f ? v0 : 0.01f * v0;
                    v1 = v1 >= 0.f ? v1 : 0.01f * v1;
                    const float* wr = wm2s + c * 16;
#pragma unroll
                    for (int m = 0; m < DX; m++) {
                        float wv = wr[m];
                        proj[2 * f][m]     += v0 * wv;
                        proj[2 * f + 1][m] += v1 * wv;
                    }
                }
            }
#pragma unroll
        for (int s2 = 0; s2 < 4; s2++)
#pragma unroll
            for (int m = 0; m < DX; m++) {
                proj[s2][m] += __shfl_xor_sync(0xFFFFFFFFu, proj[s2][m], 1);
                proj[s2][m] += __shfl_xor_sync(0xFFFFFFFFu, proj[s2][m], 2);
            }
        if ((lane & 3) == 0) {
            int slice = bn * 2 + (wid & 1);      // 8 slices (bn<4 x 2 n-groups)
#pragma unroll
            for (int s2 = 0; s2 < 4; s2++) {
                int row = bt * 128 + mw + (s2 >> 1) * 16 + (lane >> 2) + (s2 & 1) * 8;
                float* dst = g_part + ((size_t)slice * BE + row) * DX;
#pragma unroll
                for (int m = 0; m < DX; m++) dst[m] = proj[s2][m];
            }
        }
    }
}

// ---------------- sensor MLP on 2048 distinct rows ----------------
__global__ void __launch_bounds__(256)
sensor_kernel(const float* __restrict__ raw,
              const float* __restrict__ w2, const float* __restrict__ b2,
              const float* __restrict__ w3, const float* __restrict__ b3,
              const float* __restrict__ w5, const float* __restrict__ b5,
              const float* __restrict__ w6, const float* __restrict__ b6,
              float* __restrict__ sens)
{
    __shared__ float s[4][SM_IN], h1[4][256], h2[4][256], h3[4][64];
    const int tid = threadIdx.x;
    const int row0 = blockIdx.x * 4;

    for (int i = tid; i < 4 * SM_IN; i += 256)
        s[i / SM_IN][i % SM_IN] = raw[(size_t)(row0 + i / SM_IN) * SM_IN + i % SM_IN];
    __syncthreads();
    {
        float acc[4];
#pragma unroll
        for (int r = 0; r < 4; r++) acc[r] = b2[tid];
        for (int k = 0; k < SM_IN; k++) {
            float w = w2[k * 256 + tid];
#pragma unroll
            for (int r = 0; r < 4; r++) acc[r] += s[r][k] * w;
        }
#pragma unroll
        for (int r = 0; r < 4; r++) h1[r][tid] = acc[r] >= 0.f ? acc[r] : 0.01f * acc[r];
    }
    __syncthreads();
    {
        float acc[4];
#pragma unroll
        for (int r = 0; r < 4; r++) acc[r] = b3[tid];
        for (int k = 0; k < 256; k++) {
            float w = w3[k * 256 + tid];
#pragma unroll
            for (int r = 0; r < 4; r++) acc[r] += h1[r][k] * w;
        }
#pragma unroll
        for (int r = 0; r < 4; r++) h2[r][tid] = acc[r] >= 0.f ? acc[r] : 0.01f * acc[r];
    }
    __syncthreads();
    if (tid < 64) {
        float acc[4];
#pragma unroll
        for (int r = 0; r < 4; r++) acc[r] = b5[tid];
        for (int k = 0; k < 256; k++) {
            float w = w5[k * 64 + tid];
#pragma unroll
            for (int r = 0; r < 4; r++) acc[r] += h2[r][k] * w;
        }
#pragma unroll
        for (int r = 0; r < 4; r++) h3[r][tid] = acc[r] >= 0.f ? acc[r] : 0.01f * acc[r];
    }
    __syncthreads();
    if (tid < DZ) {
        float acc[4];
#pragma unroll
        for (int r = 0; r < 4; r++) acc[r] = b6[tid];
        for (int k = 0; k < 64; k++) {
            float w = w6[k * DZ + tid];
#pragma unroll
            for (int r = 0; r < 4; r++) acc[r] += h3[r][k] * w;
        }
#pragma unroll
        for (int r = 0; r < 4; r++) sens[(size_t)(row0 + r) * DZ + tid] = acc[r];
    }
}

// ---------------- EnKF per batch element ----------------
__global__ void __launch_bounds__(256)
enkf_kernel(const float* __restrict__ part, const float* __restrict__ pm_bm2,
            const float* __restrict__ sens,
            const float* __restrict__ on_w1, const float* __restrict__ on_b1,
            const float* __restrict__ on_w2, const float* __restrict__ on_b2,
            float* __restrict__ out1, float* __restrict__ out2,
            float* __restrict__ out3, float* __restrict__ out4,
            float* __restrict__ out5)
{
    const int b = blockIdx.x, tid = threadIdx.x;
    __shared__ float pred[ENS][DX], ez[ENS][DZ], Am[ENS][DX], corr[ENS][DX];
    __shared__ float sm[DX], zm[DZ], rdiag[DZ], hid[32];
    __shared__ float Mm[DX][DX], Km[DX][DZ], aug[DX][2 * DX], fac[DX];

    for (int i = tid; i < ENS * DX; i += 256) {
        int e = i / DX, j = i % DX;
        size_t row = (size_t)b * ENS + e;
        float p = pm_bm2[j];
#pragma unroll
        for (int q = 0; q < 8; q++) p += part[((size_t)q * BE + row) * DX + j];
        pred[e][j] = p;
    }
    for (int i = tid; i < ENS * DZ; i += 256) {
        int e = i / DZ, j = i % DZ;
        int src = (b * ENS + e) % BATCH;
        float v = sens[src * DZ + j];
        ez[e][j] = v;
        out5[(size_t)(b * ENS + e) * DZ + j] = v;
    }
    __syncthreads();
    if (tid < DX) {
        float s1 = 0.f, s2 = 0.f;
        for (int e = 0; e < ENS; e++) { s1 += pred[e][tid]; s2 += ez[e][tid]; }
        float m1 = s1 * (1.f / ENS), m2 = s2 * (1.f / ENS);
        sm[tid] = m1; zm[tid] = m2;
        out3[b * DX + tid] = m1;
        out4[b * DZ + tid] = m2;
    }
    __syncthreads();
    if (tid < 32) {
        float a = on_b1[tid];
        for (int i = 0; i < DZ; i++) a += zm[i] * on_w1[i * 32 + tid];
        hid[tid] = a > 0.f ? a : 0.f;
    }
    __syncthreads();
    if (tid < DZ) {
        float a = on_b2[tid];
        for (int j = 0; j < 32; j++) a += hid[j] * on_w2[j * DZ + tid];
        a += 0.001f;
        rdiag[tid] = a * a + 0.038729833f;
    }
    for (int i = tid; i < ENS * DX; i += 256)
        Am[i / DX][i % DX] = pred[i / DX][i % DX] - sm[i % DX];
    __syncthreads();
    if (tid < DX * DX) {
        int i = tid / DX, j = tid % DX;
        float s = 0.f;
        for (int e = 0; e < ENS; e++) s += Am[e][i] * Am[e][j];
        float m = s * (1.f / (ENS - 1));
        Mm[i][j] = m;
        aug[i][j] = m + (i == j ? rdiag[i] : 0.f);
        aug[i][DX + j] = (i == j) ? 1.f : 0.f;
    }
    __syncthreads();
    for (int p = 0; p < DX; p++) {
        float pv = aug[p][p];
        __syncthreads();
        if (tid < 2 * DX) aug[p][tid] *= (1.f / pv);
        if (tid < DX) fac[tid] = (tid == p) ? 0.f : aug[tid][p];
        __syncthreads();
        for (int t = tid; t < DX * 2 * DX; t += 256) {
            int rr = t / (2 * DX), c = t % (2 * DX);
            if (rr != p) aug[rr][c] -= fac[rr] * aug[p][c];
        }
        __syncthreads();
    }
    if (tid < DX * DX) {
        int i = tid / DX, j = tid % DX;
        float s = 0.f;
        for (int k = 0; k < DX; k++) s += Mm[i][k] * aug[k][DX + j];
        Km[i][j] = s;
    }
    __syncthreads();
    for (int t = tid; t < ENS * DX; t += 256) {
        int e = t / DX, i = t % DX;
        float s = pred[e][i];
        for (int j = 0; j < DZ; j++) s += Km[i][j] * (ez[e][j] - pred[e][j]);
        corr[e][i] = s;
        out1[(size_t)(b * ENS + e) * DX + i] = s;
    }
    __syncthreads();
    if (tid < DX) {
        float s = 0.f;
        for (int e = 0; e < ENS; e++) s += corr[e][tid];
        out2[b * DX + tid] = s * (1.f / ENS);
    }
}

// ---------------- launcher ----------------
extern "C" void kernel_launch(void* const* d_in, const int* in_sizes, int n_in,
                              void* d_out, int out_size)
{
    const float* raw    = (const float*)d_in[0];
    const float* sp     = (const float*)d_in[1];
    const float* pm_w1  = (const float*)d_in[2];
    const float* pm_b1  = (const float*)d_in[3];
    const float* pm_w3  = (const float*)d_in[4];
    const float* pm_b3  = (const float*)d_in[5];
    const float* pm_wm2 = (const float*)d_in[6];
    const float* pm_bm2 = (const float*)d_in[7];
    const float* sm_w2  = (const float*)d_in[8];
    const float* sm_b2  = (const float*)d_in[9];
    const float* sm_w3  = (const float*)d_in[10];
    const float* sm_b3  = (const float*)d_in[11];
    const float* sm_w5  = (const float*)d_in[12];
    const float* sm_b5  = (const float*)d_in[13];
    const float* sm_w6  = (const float*)d_in[14];
    const float* sm_b6  = (const float*)d_in[15];
    const float* on_w1  = (const float*)d_in[16];
    const float* on_b1  = (const float*)d_in[17];
    const float* on_w2  = (const float*)d_in[18];
    const float* on_b2  = (const float*)d_in[19];

    float* out = (float*)d_out;

    uint32_t *xp, *w1p, *w3p, *h1p;
    float *partp, *sensp;
    cudaGetSymbolAddress((void**)&xp,  g_x);
    cudaGetSymbolAddress((void**)&w1p, g_w1);
    cudaGetSymbolAddress((void**)&w3p, g_w3);
    cudaGetSymbolAddress((void**)&h1p, g_h1);
    cudaGetSymbolAddress((void**)&partp, g_part);
    cudaGetSymbolAddress((void**)&sensp, g_sens);

    cudaFuncSetAttribute(gemm_hmma<3, 0>, cudaFuncAttributeMaxDynamicSharedMemorySize, DYN_SMEM);
    cudaFuncSetAttribute(gemm_hmma<4, 1>, cudaFuncAttributeMaxDynamicSharedMemorySize, DYN_SMEM);

    prep_w_kernel<<<(256 * 96 + 512 * 128 + 255) / 256, 256>>>(pm_w1, pm_w3);
    prep_x_kernel<<<BE * 96 / 256, 256>>>(sp);

    // GEMM A: h1 = leaky(x @ w1 + b1)  [BE x 256], K=192 (padded)
    gemm_hmma<3, 0><<<dim3(2, BE / 128), 256, DYN_SMEM>>>(xp, w1p, 96, pm_b1, nullptr);
    // GEMM B: fused leaky(h1 @ w3 + b3) @ wm2 -> partials, K=256
    gemm_hmma<4, 1><<<dim3(4, BE / 128), 256, DYN_SMEM>>>(h1p, w3p, 128, pm_b3, pm_wm2);

    sensor_kernel<<<BATCH / 4, 256>>>(raw, sm_w2, sm_b2, sm_w3, sm_b3,
                                      sm_w5, sm_b5, sm_w6, sm_b6, sensp);
    enkf_kernel<<<BATCH, 256>>>(partp, pm_bm2, sensp, on_w1, on_b1, on_w2, on_b2,
                                out + O1_OFF, out + O2_OFF, out + O3_OFF,
                                out + O4_OFF, out + O5_OFF);
}